// round 1
// baseline (speedup 1.0000x reference)
#include <cuda_runtime.h>
#include <cstdint>

#define N_SVC  50000
#define N_NODE 20000
#define N_POD  100000
#define FDIM   128
#define ODIM   64

// ---------------- scratch (device globals; no runtime allocation) ----------------
__device__ float g_deg_svc_s[N_SVC];
__device__ float g_deg_svc_d[N_SVC];
__device__ float g_deg_pn_s[N_POD];
__device__ float g_deg_pn_d[N_NODE];
__device__ float g_deg_np_s[N_NODE];
__device__ float g_deg_np_d[N_POD];

__device__ float g_xn_svc [(size_t)N_SVC  * FDIM];
__device__ float g_xn_pod [(size_t)N_POD  * FDIM];
__device__ float g_xn_node[(size_t)N_NODE * FDIM];
__device__ float g_agg_svc [(size_t)N_SVC  * FDIM];
__device__ float g_agg_node[(size_t)N_NODE * FDIM];
__device__ float g_agg_pod [(size_t)N_POD  * FDIM];

// ---------------- kernels ----------------

__global__ void zero_kernel(float4* __restrict__ p, int n4) {
    int i = blockIdx.x * blockDim.x + threadIdx.x;
    if (i < n4) p[i] = make_float4(0.f, 0.f, 0.f, 0.f);
}

__global__ void deg_kernel(const int* __restrict__ src, const int* __restrict__ dst,
                           int E, float* __restrict__ ds, float* __restrict__ dd) {
    int i = blockIdx.x * blockDim.x + threadIdx.x;
    if (i < E) {
        atomicAdd(ds + src[i], 1.0f);
        atomicAdd(dd + dst[i], 1.0f);
    }
}

// xn = x * rsqrt(max(deg_src, 1))
__global__ void norm_kernel(const float* __restrict__ x, const float* __restrict__ deg,
                            float* __restrict__ xn, int n) {
    int i = blockIdx.x * blockDim.x + threadIdx.x;   // over n*32 float4s
    if (i >= n * (FDIM / 4)) return;
    int row = i >> 5;
    float d = deg[row];
    float s = rsqrtf(d > 1.0f ? d : 1.0f);
    float4 v = ((const float4*)x)[i];
    v.x *= s; v.y *= s; v.z *= s; v.w *= s;
    ((float4*)xn)[i] = v;
}

// one warp per edge: gather xn[src] (128B/lane-group), RED.v4.f32 into agg[dst]
__global__ void scatter_kernel(const float* __restrict__ xn, const int* __restrict__ src,
                               const int* __restrict__ dst, int E, float* __restrict__ agg) {
    int g = blockIdx.x * blockDim.x + threadIdx.x;
    int e = g >> 5;
    int lane = g & 31;
    if (e >= E) return;
    int s = __ldg(&src[e]);
    int d = __ldg(&dst[e]);
    float4 v = ((const float4*)(xn + (size_t)s * FDIM))[lane];
    float* p = agg + (size_t)d * FDIM + lane * 4;
    asm volatile("red.global.add.v4.f32 [%0], {%1,%2,%3,%4};"
                 :: "l"(p), "f"(v.x), "f"(v.y), "f"(v.z), "f"(v.w) : "memory");
}

// fused: out = leaky( (agg * rsqrt(max(deg_dst,1))) @ W + b ) @ Wl + bl
// block = 256 thr, tile = 128 rows x 128 hidden; 8x8 register tiling stage1,
// 8x4 stage2. W, Wl, A-tile, H-tile all in smem.
#define SA_LD 132   // padded row stride (floats); 132*4B keeps float4 alignment

__global__ __launch_bounds__(256, 1)
void fused_out_kernel(const float* __restrict__ agg, const float* __restrict__ degd,
                      const float* __restrict__ W, const float* __restrict__ b,
                      const float* __restrict__ Wl, const float* __restrict__ bl,
                      float* __restrict__ out, int nrows) {
    extern __shared__ float sm[];
    float* sA  = sm;                         // 128 * 132
    float* sW  = sA + 128 * SA_LD;           // 128 * 128
    float* sWl = sW + 128 * 128;             // 128 * 64
    float* sB  = sWl + 128 * 64;             // 128
    float* sBl = sB + 128;                   // 64

    const int t = threadIdx.x;
    const int row0 = blockIdx.x * 128;

    // cooperative loads of weights/biases
    for (int i = t; i < (128 * 128) / 4; i += 256)
        ((float4*)sW)[i] = ((const float4*)W)[i];
    for (int i = t; i < (128 * 64) / 4; i += 256)
        ((float4*)sWl)[i] = ((const float4*)Wl)[i];
    if (t < 128) sB[t] = b[t];
    if (t < 64)  sBl[t] = bl[t];

    // A tile, scaled by rsqrt(deg_dst), zero-padded past nrows
    for (int i = t; i < 128 * (FDIM / 4); i += 256) {
        int r  = i >> 5;
        int c4 = i & 31;
        float4 v = make_float4(0.f, 0.f, 0.f, 0.f);
        int gr = row0 + r;
        if (gr < nrows) {
            float d = degd[gr];
            float s = rsqrtf(d > 1.0f ? d : 1.0f);
            v = ((const float4*)(agg + (size_t)gr * FDIM))[c4];
            v.x *= s; v.y *= s; v.z *= s; v.w *= s;
        }
        *((float4*)(sA + r * SA_LD + c4 * 4)) = v;
    }
    __syncthreads();

    const int tcol = t & 15;     // 16 column-threads
    const int trow = t >> 4;     // 16 row-threads
    const int j0 = tcol * 8;
    const int r0 = trow * 8;

    // ---- stage 1: H = A @ W + b ----
    float acc[8][8];
    #pragma unroll
    for (int rr = 0; rr < 8; ++rr)
        #pragma unroll
        for (int jj = 0; jj < 8; ++jj)
            acc[rr][jj] = sB[j0 + jj];

    #pragma unroll 2
    for (int k = 0; k < 128; ++k) {
        float a[8], w[8];
        #pragma unroll
        for (int rr = 0; rr < 8; ++rr) a[rr] = sA[(r0 + rr) * SA_LD + k];
        float4 w0 = *(const float4*)(sW + (k << 7) + j0);
        float4 w1 = *(const float4*)(sW + (k << 7) + j0 + 4);
        w[0] = w0.x; w[1] = w0.y; w[2] = w0.z; w[3] = w0.w;
        w[4] = w1.x; w[5] = w1.y; w[6] = w1.z; w[7] = w1.w;
        #pragma unroll
        for (int rr = 0; rr < 8; ++rr)
            #pragma unroll
            for (int jj = 0; jj < 8; ++jj)
                acc[rr][jj] = fmaf(a[rr], w[jj], acc[rr][jj]);
    }
    __syncthreads();   // everyone done reading sA

    // leaky + write H back into sA
    #pragma unroll
    for (int rr = 0; rr < 8; ++rr) {
        float4 h0, h1;
        float h;
        h = acc[rr][0]; h0.x = h > 0.f ? h : 0.01f * h;
        h = acc[rr][1]; h0.y = h > 0.f ? h : 0.01f * h;
        h = acc[rr][2]; h0.z = h > 0.f ? h : 0.01f * h;
        h = acc[rr][3]; h0.w = h > 0.f ? h : 0.01f * h;
        h = acc[rr][4]; h1.x = h > 0.f ? h : 0.01f * h;
        h = acc[rr][5]; h1.y = h > 0.f ? h : 0.01f * h;
        h = acc[rr][6]; h1.z = h > 0.f ? h : 0.01f * h;
        h = acc[rr][7]; h1.w = h > 0.f ? h : 0.01f * h;
        *((float4*)(sA + (r0 + rr) * SA_LD + j0))     = h0;
        *((float4*)(sA + (r0 + rr) * SA_LD + j0 + 4)) = h1;
    }
    __syncthreads();

    // ---- stage 2: out = H @ Wl + bl ----
    const int oc0 = tcol * 4;    // 16 * 4 = 64 output cols
    float acc2[8][4];
    #pragma unroll
    for (int rr = 0; rr < 8; ++rr)
        #pragma unroll
        for (int cc = 0; cc < 4; ++cc)
            acc2[rr][cc] = sBl[oc0 + cc];

    #pragma unroll 2
    for (int k = 0; k < 128; ++k) {
        float hfrag[8];
        #pragma unroll
        for (int rr = 0; rr < 8; ++rr) hfrag[rr] = sA[(r0 + rr) * SA_LD + k];
        float4 wl = *(const float4*)(sWl + (k << 6) + oc0);
        #pragma unroll
        for (int rr = 0; rr < 8; ++rr) {
            acc2[rr][0] = fmaf(hfrag[rr], wl.x, acc2[rr][0]);
            acc2[rr][1] = fmaf(hfrag[rr], wl.y, acc2[rr][1]);
            acc2[rr][2] = fmaf(hfrag[rr], wl.z, acc2[rr][2]);
            acc2[rr][3] = fmaf(hfrag[rr], wl.w, acc2[rr][3]);
        }
    }

    #pragma unroll
    for (int rr = 0; rr < 8; ++rr) {
        int gr = row0 + r0 + rr;
        if (gr < nrows) {
            float4 o = make_float4(acc2[rr][0], acc2[rr][1], acc2[rr][2], acc2[rr][3]);
            *((float4*)(out + (size_t)gr * ODIM + oc0)) = o;
        }
    }
}

// ---------------- host launcher ----------------

static inline int cdiv(long long a, long long b) { return (int)((a + b - 1) / b); }

extern "C" void kernel_launch(void* const* d_in, const int* in_sizes, int n_in,
                              void* d_out, int out_size) {
    const float* x_svc  = (const float*)d_in[0];
    const float* x_pod  = (const float*)d_in[1];
    const float* x_node = (const float*)d_in[2];
    const int* svc_src = (const int*)d_in[3];
    const int* svc_dst = (const int*)d_in[4];
    const int* pn_src  = (const int*)d_in[5];
    const int* pn_dst  = (const int*)d_in[6];
    const int* np_src  = (const int*)d_in[7];
    const int* np_dst  = (const int*)d_in[8];
    const float* W_call = (const float*)d_in[9];
    const float* b_call = (const float*)d_in[10];
    const float* W_in   = (const float*)d_in[11];
    const float* b_in   = (const float*)d_in[12];
    const float* W_ni   = (const float*)d_in[13];
    const float* b_ni   = (const float*)d_in[14];
    const float* W_lin_svc  = (const float*)d_in[15];
    const float* b_lin_svc  = (const float*)d_in[16];
    const float* W_lin_node = (const float*)d_in[17];
    const float* b_lin_node = (const float*)d_in[18];
    const float* W_lin_pod  = (const float*)d_in[19];
    const float* b_lin_pod  = (const float*)d_in[20];
    float* out = (float*)d_out;

    const int E_SVC = in_sizes[3];
    const int E_PN  = in_sizes[5];
    const int E_NP  = in_sizes[7];

    // resolve scratch symbol addresses (host-side query; capture-safe)
    float *deg_svc_s, *deg_svc_d, *deg_pn_s, *deg_pn_d, *deg_np_s, *deg_np_d;
    float *xn_svc, *xn_pod, *xn_node, *agg_svc, *agg_node, *agg_pod;
    cudaGetSymbolAddress((void**)&deg_svc_s, g_deg_svc_s);
    cudaGetSymbolAddress((void**)&deg_svc_d, g_deg_svc_d);
    cudaGetSymbolAddress((void**)&deg_pn_s,  g_deg_pn_s);
    cudaGetSymbolAddress((void**)&deg_pn_d,  g_deg_pn_d);
    cudaGetSymbolAddress((void**)&deg_np_s,  g_deg_np_s);
    cudaGetSymbolAddress((void**)&deg_np_d,  g_deg_np_d);
    cudaGetSymbolAddress((void**)&xn_svc,  g_xn_svc);
    cudaGetSymbolAddress((void**)&xn_pod,  g_xn_pod);
    cudaGetSymbolAddress((void**)&xn_node, g_xn_node);
    cudaGetSymbolAddress((void**)&agg_svc,  g_agg_svc);
    cudaGetSymbolAddress((void**)&agg_node, g_agg_node);
    cudaGetSymbolAddress((void**)&agg_pod,  g_agg_pod);

    const int TB = 256;

    // 1) zero degree + agg scratch
    auto zero = [&](float* p, long long n) {
        int n4 = (int)(n / 4);
        zero_kernel<<<cdiv(n4, TB), TB>>>((float4*)p, n4);
    };
    zero(deg_svc_s, N_SVC); zero(deg_svc_d, N_SVC);
    zero(deg_pn_s, N_POD);  zero(deg_pn_d, N_NODE);
    zero(deg_np_s, N_NODE); zero(deg_np_d, N_POD);
    zero(agg_svc,  (long long)N_SVC * FDIM);
    zero(agg_node, (long long)N_NODE * FDIM);
    zero(agg_pod,  (long long)N_POD * FDIM);

    // 2) degrees
    deg_kernel<<<cdiv(E_SVC, TB), TB>>>(svc_src, svc_dst, E_SVC, deg_svc_s, deg_svc_d);
    deg_kernel<<<cdiv(E_PN,  TB), TB>>>(pn_src,  pn_dst,  E_PN,  deg_pn_s,  deg_pn_d);
    deg_kernel<<<cdiv(E_NP,  TB), TB>>>(np_src,  np_dst,  E_NP,  deg_np_s,  deg_np_d);

    // 3) source-side normalization
    norm_kernel<<<cdiv((long long)N_SVC * 32, TB), TB>>>(x_svc,  deg_svc_s, xn_svc,  N_SVC);
    norm_kernel<<<cdiv((long long)N_POD * 32, TB), TB>>>(x_pod,  deg_pn_s,  xn_pod,  N_POD);
    norm_kernel<<<cdiv((long long)N_NODE * 32, TB), TB>>>(x_node, deg_np_s,  xn_node, N_NODE);

    // 4) gather + atomic scatter-sum (warp per edge)
    scatter_kernel<<<cdiv((long long)E_SVC * 32, TB), TB>>>(xn_svc,  svc_src, svc_dst, E_SVC, agg_svc);
    scatter_kernel<<<cdiv((long long)E_PN  * 32, TB), TB>>>(xn_pod,  pn_src,  pn_dst,  E_PN,  agg_node);
    scatter_kernel<<<cdiv((long long)E_NP  * 32, TB), TB>>>(xn_node, np_src,  np_dst,  E_NP,  agg_pod);

    // 5) fused dst-norm + GEMM + leaky + linear, writing concat [svc; node; pod]
    const int SMEM = (128 * SA_LD + 128 * 128 + 128 * 64 + 128 + 64) * (int)sizeof(float);
    cudaFuncSetAttribute(fused_out_kernel, cudaFuncAttributeMaxDynamicSharedMemorySize, SMEM);

    fused_out_kernel<<<cdiv(N_SVC, 128), 256, SMEM>>>(
        agg_svc, deg_svc_d, W_call, b_call, W_lin_svc, b_lin_svc,
        out + 0, N_SVC);
    fused_out_kernel<<<cdiv(N_NODE, 128), 256, SMEM>>>(
        agg_node, deg_pn_d, W_in, b_in, W_lin_node, b_lin_node,
        out + (size_t)N_SVC * ODIM, N_NODE);
    fused_out_kernel<<<cdiv(N_POD, 128), 256, SMEM>>>(
        agg_pod, deg_np_d, W_ni, b_ni, W_lin_pod, b_lin_pod,
        out + (size_t)(N_SVC + N_NODE) * ODIM, N_POD);
}

// round 2
// speedup vs baseline: 1.0956x; 1.0956x over previous
#include <cuda_runtime.h>
#include <cstdint>

#define N_SVC  50000
#define N_NODE 20000
#define N_POD  100000
#define FDIM   128
#define ODIM   64

// ---------------- scratch (device globals; no runtime allocation) ----------------
__device__ float g_deg_svc_s[N_SVC];
__device__ float g_deg_svc_d[N_SVC];
__device__ float g_deg_pn_s[N_POD];
__device__ float g_deg_pn_d[N_NODE];
__device__ float g_deg_np_s[N_NODE];
__device__ float g_deg_np_d[N_POD];

__device__ float g_agg_svc [(size_t)N_SVC  * FDIM];
__device__ float g_agg_node[(size_t)N_NODE * FDIM];
__device__ float g_agg_pod [(size_t)N_POD  * FDIM];

// ---------------- f32x2 helpers ----------------
__device__ __forceinline__ unsigned long long pack2(float lo, float hi) {
    unsigned long long r;
    asm("mov.b64 %0, {%1, %2};" : "=l"(r) : "f"(lo), "f"(hi));
    return r;
}
__device__ __forceinline__ void unpack2(unsigned long long v, float& lo, float& hi) {
    asm("mov.b64 {%0, %1}, %2;" : "=f"(lo), "=f"(hi) : "l"(v));
}
__device__ __forceinline__ unsigned long long fma2(unsigned long long a,
                                                   unsigned long long b,
                                                   unsigned long long c) {
    unsigned long long d;
    asm("fma.rn.f32x2 %0, %1, %2, %3;" : "=l"(d) : "l"(a), "l"(b), "l"(c));
    return d;
}

// ---------------- kernels ----------------

// one launch zeroes all scratch
__global__ void zero_all_kernel() {
    const size_t T = (size_t)gridDim.x * blockDim.x;
    const size_t i0 = (size_t)blockIdx.x * blockDim.x + threadIdx.x;
    const float4 z = make_float4(0.f, 0.f, 0.f, 0.f);
    for (size_t i = i0; i < (size_t)N_SVC  * FDIM / 4; i += T) ((float4*)g_agg_svc)[i]  = z;
    for (size_t i = i0; i < (size_t)N_NODE * FDIM / 4; i += T) ((float4*)g_agg_node)[i] = z;
    for (size_t i = i0; i < (size_t)N_POD  * FDIM / 4; i += T) ((float4*)g_agg_pod)[i]  = z;
    for (size_t i = i0; i < N_SVC;  i += T) { g_deg_svc_s[i] = 0.f; g_deg_svc_d[i] = 0.f; }
    for (size_t i = i0; i < N_POD;  i += T) { g_deg_pn_s[i]  = 0.f; g_deg_np_d[i]  = 0.f; }
    for (size_t i = i0; i < N_NODE; i += T) { g_deg_pn_d[i]  = 0.f; g_deg_np_s[i]  = 0.f; }
}

// all three edge types' degree histograms in one launch
__global__ void deg_all_kernel(const int* __restrict__ svc_src, const int* __restrict__ svc_dst,
                               const int* __restrict__ pn_src,  const int* __restrict__ pn_dst,
                               const int* __restrict__ np_src,  const int* __restrict__ np_dst,
                               int E_SVC, int E_PN, int E_NP) {
    int i = blockIdx.x * blockDim.x + threadIdx.x;
    if (i < E_SVC) {
        atomicAdd(g_deg_svc_s + svc_src[i], 1.0f);
        atomicAdd(g_deg_svc_d + svc_dst[i], 1.0f);
        return;
    }
    i -= E_SVC;
    if (i < E_PN) {
        atomicAdd(g_deg_pn_s + pn_src[i], 1.0f);
        atomicAdd(g_deg_pn_d + pn_dst[i], 1.0f);
        return;
    }
    i -= E_PN;
    if (i < E_NP) {
        atomicAdd(g_deg_np_s + np_src[i], 1.0f);
        atomicAdd(g_deg_np_d + np_dst[i], 1.0f);
    }
}

// convert all degree arrays to rsqrt(max(deg,1)) in place
__global__ void rs_all_kernel() {
    int i = blockIdx.x * blockDim.x + threadIdx.x;
    if (i < N_SVC) {
        g_deg_svc_s[i] = rsqrtf(fmaxf(g_deg_svc_s[i], 1.f));
        g_deg_svc_d[i] = rsqrtf(fmaxf(g_deg_svc_d[i], 1.f));
    }
    if (i < N_POD) {
        g_deg_pn_s[i] = rsqrtf(fmaxf(g_deg_pn_s[i], 1.f));
        g_deg_np_d[i] = rsqrtf(fmaxf(g_deg_np_d[i], 1.f));
    }
    if (i < N_NODE) {
        g_deg_pn_d[i] = rsqrtf(fmaxf(g_deg_pn_d[i], 1.f));
        g_deg_np_s[i] = rsqrtf(fmaxf(g_deg_np_s[i], 1.f));
    }
}

// warp handles 2 edges: gather x[src]*rs_src[src] (128B per lane-group), RED.v4 into agg[dst]
__global__ void scatter_kernel(const float* __restrict__ x, const float* __restrict__ rs,
                               const int* __restrict__ src, const int* __restrict__ dst,
                               int E, float* __restrict__ agg) {
    int g = blockIdx.x * blockDim.x + threadIdx.x;
    int w = g >> 5;
    int lane = g & 31;
    int e0 = w * 2;
    if (e0 >= E) return;
    int e1 = e0 + 1;
    bool has1 = (e1 < E);

    int s0 = __ldg(src + e0);
    int d0 = __ldg(dst + e0);
    int s1 = has1 ? __ldg(src + e1) : s0;
    int d1 = has1 ? __ldg(dst + e1) : d0;

    float sc0 = __ldg(rs + s0);
    float sc1 = __ldg(rs + s1);
    float4 v0 = ((const float4*)(x + (size_t)s0 * FDIM))[lane];
    float4 v1 = ((const float4*)(x + (size_t)s1 * FDIM))[lane];

    v0.x *= sc0; v0.y *= sc0; v0.z *= sc0; v0.w *= sc0;
    float* p0 = agg + (size_t)d0 * FDIM + lane * 4;
    asm volatile("red.global.add.v4.f32 [%0], {%1,%2,%3,%4};"
                 :: "l"(p0), "f"(v0.x), "f"(v0.y), "f"(v0.z), "f"(v0.w) : "memory");

    if (has1) {
        v1.x *= sc1; v1.y *= sc1; v1.z *= sc1; v1.w *= sc1;
        float* p1 = agg + (size_t)d1 * FDIM + lane * 4;
        asm volatile("red.global.add.v4.f32 [%0], {%1,%2,%3,%4};"
                     :: "l"(p1), "f"(v1.x), "f"(v1.y), "f"(v1.z), "f"(v1.w) : "memory");
    }
}

// fused: out = leaky( (agg * rs_dst) @ W + b ) @ Wl + bl   — f32x2 packed FMA
#define SA_LD 132   // padded row stride (floats)

__global__ __launch_bounds__(256, 1)
void fused_out_kernel(const float* __restrict__ agg, const float* __restrict__ rsd,
                      const float* __restrict__ W, const float* __restrict__ b,
                      const float* __restrict__ Wl, const float* __restrict__ bl,
                      float* __restrict__ out, int nrows) {
    extern __shared__ float sm[];
    float* sA  = sm;                         // 128 * 132
    float* sW  = sA + 128 * SA_LD;           // 128 * 128   (offset 16B aligned)
    float* sWl = sW + 128 * 128;             // 128 * 64
    float* sB  = sWl + 128 * 64;             // 128
    float* sBl = sB + 128;                   // 64

    const int t = threadIdx.x;
    const int row0 = blockIdx.x * 128;

    for (int i = t; i < (128 * 128) / 4; i += 256)
        ((float4*)sW)[i] = ((const float4*)W)[i];
    for (int i = t; i < (128 * 64) / 4; i += 256)
        ((float4*)sWl)[i] = ((const float4*)Wl)[i];
    if (t < 128) sB[t] = b[t];
    if (t < 64)  sBl[t] = bl[t];

    // A tile, scaled by rsqrt-deg(dst), zero-padded past nrows
    for (int i = t; i < 128 * (FDIM / 4); i += 256) {
        int r  = i >> 5;
        int c4 = i & 31;
        float4 v = make_float4(0.f, 0.f, 0.f, 0.f);
        int gr = row0 + r;
        if (gr < nrows) {
            float s = rsd[gr];
            v = ((const float4*)(agg + (size_t)gr * FDIM))[c4];
            v.x *= s; v.y *= s; v.z *= s; v.w *= s;
        }
        *((float4*)(sA + r * SA_LD + c4 * 4)) = v;
    }
    __syncthreads();

    const int tcol = t & 15;     // 16 column-threads
    const int trow = t >> 4;     // 16 row-threads
    const int j0 = tcol * 8;
    const int r0 = trow * 8;

    // ---- stage 1: H = A @ W + b  (8 rows x 4 col-pairs, f32x2) ----
    unsigned long long acc[8][4];
    {
        const ulonglong2* pb = (const ulonglong2*)(sB + j0);   // 32B aligned
        ulonglong2 b01 = pb[0];
        ulonglong2 b23 = pb[1];
        #pragma unroll
        for (int rr = 0; rr < 8; ++rr) {
            acc[rr][0] = b01.x; acc[rr][1] = b01.y;
            acc[rr][2] = b23.x; acc[rr][3] = b23.y;
        }
    }

    #pragma unroll 2
    for (int k = 0; k < 128; ++k) {
        unsigned long long aa[8];
        #pragma unroll
        for (int rr = 0; rr < 8; ++rr) {
            float a = sA[(r0 + rr) * SA_LD + k];
            aa[rr] = pack2(a, a);
        }
        ulonglong2 w01 = *(const ulonglong2*)(sW + (k << 7) + j0);
        ulonglong2 w23 = *(const ulonglong2*)(sW + (k << 7) + j0 + 4);
        #pragma unroll
        for (int rr = 0; rr < 8; ++rr) {
            acc[rr][0] = fma2(aa[rr], w01.x, acc[rr][0]);
            acc[rr][1] = fma2(aa[rr], w01.y, acc[rr][1]);
            acc[rr][2] = fma2(aa[rr], w23.x, acc[rr][2]);
            acc[rr][3] = fma2(aa[rr], w23.y, acc[rr][3]);
        }
    }
    __syncthreads();   // everyone done reading sA

    // leaky + write H back into sA (row-major)
    #pragma unroll
    for (int rr = 0; rr < 8; ++rr) {
        float h[8];
        unpack2(acc[rr][0], h[0], h[1]);
        unpack2(acc[rr][1], h[2], h[3]);
        unpack2(acc[rr][2], h[4], h[5]);
        unpack2(acc[rr][3], h[6], h[7]);
        #pragma unroll
        for (int q = 0; q < 8; ++q) h[q] = h[q] > 0.f ? h[q] : 0.01f * h[q];
        float4 h0 = make_float4(h[0], h[1], h[2], h[3]);
        float4 h1 = make_float4(h[4], h[5], h[6], h[7]);
        *((float4*)(sA + (r0 + rr) * SA_LD + j0))     = h0;
        *((float4*)(sA + (r0 + rr) * SA_LD + j0 + 4)) = h1;
    }
    __syncthreads();

    // ---- stage 2: out = H @ Wl + bl  (8 rows x 2 col-pairs, f32x2) ----
    const int oc0 = tcol * 4;    // 16 * 4 = 64 output cols
    unsigned long long acc2[8][2];
    {
        ulonglong2 bl2 = *(const ulonglong2*)(sBl + oc0);      // 16B aligned
        #pragma unroll
        for (int rr = 0; rr < 8; ++rr) { acc2[rr][0] = bl2.x; acc2[rr][1] = bl2.y; }
    }

    #pragma unroll 2
    for (int k = 0; k < 128; ++k) {
        unsigned long long hh[8];
        #pragma unroll
        for (int rr = 0; rr < 8; ++rr) {
            float h = sA[(r0 + rr) * SA_LD + k];
            hh[rr] = pack2(h, h);
        }
        ulonglong2 wl = *(const ulonglong2*)(sWl + (k << 6) + oc0);
        #pragma unroll
        for (int rr = 0; rr < 8; ++rr) {
            acc2[rr][0] = fma2(hh[rr], wl.x, acc2[rr][0]);
            acc2[rr][1] = fma2(hh[rr], wl.y, acc2[rr][1]);
        }
    }

    #pragma unroll
    for (int rr = 0; rr < 8; ++rr) {
        int gr = row0 + r0 + rr;
        if (gr < nrows) {
            float o[4];
            unpack2(acc2[rr][0], o[0], o[1]);
            unpack2(acc2[rr][1], o[2], o[3]);
            *((float4*)(out + (size_t)gr * ODIM + oc0)) =
                make_float4(o[0], o[1], o[2], o[3]);
        }
    }
}

// ---------------- host launcher ----------------

static inline int cdiv(long long a, long long b) { return (int)((a + b - 1) / b); }

extern "C" void kernel_launch(void* const* d_in, const int* in_sizes, int n_in,
                              void* d_out, int out_size) {
    const float* x_svc  = (const float*)d_in[0];
    const float* x_pod  = (const float*)d_in[1];
    const float* x_node = (const float*)d_in[2];
    const int* svc_src = (const int*)d_in[3];
    const int* svc_dst = (const int*)d_in[4];
    const int* pn_src  = (const int*)d_in[5];
    const int* pn_dst  = (const int*)d_in[6];
    const int* np_src  = (const int*)d_in[7];
    const int* np_dst  = (const int*)d_in[8];
    const float* W_call = (const float*)d_in[9];
    const float* b_call = (const float*)d_in[10];
    const float* W_in   = (const float*)d_in[11];
    const float* b_in   = (const float*)d_in[12];
    const float* W_ni   = (const float*)d_in[13];
    const float* b_ni   = (const float*)d_in[14];
    const float* W_lin_svc  = (const float*)d_in[15];
    const float* b_lin_svc  = (const float*)d_in[16];
    const float* W_lin_node = (const float*)d_in[17];
    const float* b_lin_node = (const float*)d_in[18];
    const float* W_lin_pod  = (const float*)d_in[19];
    const float* b_lin_pod  = (const float*)d_in[20];
    float* out = (float*)d_out;

    const int E_SVC = in_sizes[3];
    const int E_PN  = in_sizes[5];
    const int E_NP  = in_sizes[7];

    float *rs_svc_s, *rs_svc_d, *rs_pn_s, *rs_pn_d, *rs_np_s, *rs_np_d;
    float *agg_svc, *agg_node, *agg_pod;
    cudaGetSymbolAddress((void**)&rs_svc_s, g_deg_svc_s);
    cudaGetSymbolAddress((void**)&rs_svc_d, g_deg_svc_d);
    cudaGetSymbolAddress((void**)&rs_pn_s,  g_deg_pn_s);
    cudaGetSymbolAddress((void**)&rs_pn_d,  g_deg_pn_d);
    cudaGetSymbolAddress((void**)&rs_np_s,  g_deg_np_s);
    cudaGetSymbolAddress((void**)&rs_np_d,  g_deg_np_d);
    cudaGetSymbolAddress((void**)&agg_svc,  g_agg_svc);
    cudaGetSymbolAddress((void**)&agg_node, g_agg_node);
    cudaGetSymbolAddress((void**)&agg_pod,  g_agg_pod);

    const int TB = 256;

    // launch 0: zero all scratch
    zero_all_kernel<<<1024, TB>>>();

    // launch 1: degrees (all edge types)
    deg_all_kernel<<<cdiv((long long)E_SVC + E_PN + E_NP, TB), TB>>>(
        svc_src, svc_dst, pn_src, pn_dst, np_src, np_dst, E_SVC, E_PN, E_NP);

    // launch 2: deg -> rsqrt in place
    rs_all_kernel<<<cdiv(N_POD, TB), TB>>>();

    // launches 3,4: small scatters; launch 5: big svc scatter (ncu -s 5 -c 1 target)
    scatter_kernel<<<cdiv((long long)cdiv(E_PN, 2) * 32, TB), TB>>>(
        x_pod, rs_pn_s, pn_src, pn_dst, E_PN, agg_node);
    scatter_kernel<<<cdiv((long long)cdiv(E_NP, 2) * 32, TB), TB>>>(
        x_node, rs_np_s, np_src, np_dst, E_NP, agg_pod);
    scatter_kernel<<<cdiv((long long)cdiv(E_SVC, 2) * 32, TB), TB>>>(
        x_svc, rs_svc_s, svc_src, svc_dst, E_SVC, agg_svc);

    // launches 6-8: fused dst-norm + GEMM + leaky + linear, concat [svc; node; pod]
    const int SMEM = (128 * SA_LD + 128 * 128 + 128 * 64 + 128 + 64) * (int)sizeof(float);
    cudaFuncSetAttribute(fused_out_kernel, cudaFuncAttributeMaxDynamicSharedMemorySize, SMEM);

    fused_out_kernel<<<cdiv(N_SVC, 128), 256, SMEM>>>(
        agg_svc, rs_svc_d, W_call, b_call, W_lin_svc, b_lin_svc,
        out + 0, N_SVC);
    fused_out_kernel<<<cdiv(N_NODE, 128), 256, SMEM>>>(
        agg_node, rs_pn_d, W_in, b_in, W_lin_node, b_lin_node,
        out + (size_t)N_SVC * ODIM, N_NODE);
    fused_out_kernel<<<cdiv(N_POD, 128), 256, SMEM>>>(
        agg_pod, rs_np_d, W_ni, b_ni, W_lin_pod, b_lin_pod,
        out + (size_t)(N_SVC + N_NODE) * ODIM, N_POD);
}

// round 4
// speedup vs baseline: 1.4771x; 1.3482x over previous
#include <cuda_runtime.h>
#include <cstdint>

#define N_SVC  50000
#define N_NODE 20000
#define N_POD  100000
#define FDIM   128
#define ODIM   64
#define E_SVC_CAP 1600000
#define E_SM_CAP  100000

// ---------------- scratch (device globals; zero-init at load; re-zeroed by cleanup) ----
__device__ int g_cs_svc[N_SVC];     // src degree (svc->svc)
__device__ int g_cd_svc[N_SVC];     // dst degree
__device__ int g_cs_pn[N_POD];      // src degree (pod->node)
__device__ int g_cd_pn[N_NODE];
__device__ int g_cs_np[N_NODE];     // src degree (node->pod)
__device__ int g_cd_np[N_POD];
__device__ int g_tot[3];

__device__ float g_rss_svc[N_SVC];
__device__ float g_rsd_svc[N_SVC];
__device__ float g_rss_pn[N_POD];
__device__ float g_rsd_pn[N_NODE];
__device__ float g_rss_np[N_NODE];
__device__ float g_rsd_np[N_POD];

__device__ int g_off_svc[N_SVC];
__device__ int g_cur_svc[N_SVC];
__device__ int g_srt_svc[E_SVC_CAP];
__device__ int g_off_pn[N_NODE];
__device__ int g_cur_pn[N_NODE];
__device__ int g_srt_pn[E_SM_CAP];
__device__ int g_off_np[N_POD];
__device__ int g_cur_np[N_POD];
__device__ int g_srt_np[E_SM_CAP];

__device__ float g_agg_svc [(size_t)N_SVC  * FDIM];
__device__ float g_agg_node[(size_t)N_NODE * FDIM];
__device__ float g_agg_pod [(size_t)N_POD  * FDIM];

// ---------------- f32x2 helpers ----------------
__device__ __forceinline__ unsigned long long pack2(float lo, float hi) {
    unsigned long long r;
    asm("mov.b64 %0, {%1, %2};" : "=l"(r) : "f"(lo), "f"(hi));
    return r;
}
__device__ __forceinline__ void unpack2(unsigned long long v, float& lo, float& hi) {
    asm("mov.b64 {%0, %1}, %2;" : "=f"(lo), "=f"(hi) : "l"(v));
}
__device__ __forceinline__ unsigned long long fma2(unsigned long long a,
                                                   unsigned long long b,
                                                   unsigned long long c) {
    unsigned long long d;
    asm("fma.rn.f32x2 %0, %1, %2, %3;" : "=l"(d) : "l"(a), "l"(b), "l"(c));
    return d;
}

// ---------------- build kernels ----------------

// launch 0: degree counts for all 3 edge types
__global__ void cnt_all_kernel(const int* __restrict__ ss, const int* __restrict__ sd,
                               const int* __restrict__ ps, const int* __restrict__ pd,
                               const int* __restrict__ ns, const int* __restrict__ nd,
                               int Es, int Ep, int En) {
    int i = blockIdx.x * blockDim.x + threadIdx.x;
    if (i < Es) {
        atomicAdd(g_cs_svc + ss[i], 1);
        atomicAdd(g_cd_svc + sd[i], 1);
        return;
    }
    i -= Es;
    if (i < Ep) {
        atomicAdd(g_cs_pn + ps[i], 1);
        atomicAdd(g_cd_pn + pd[i], 1);
        return;
    }
    i -= Ep;
    if (i < En) {
        atomicAdd(g_cs_np + ns[i], 1);
        atomicAdd(g_cd_np + nd[i], 1);
    }
}

// launch 1: rs arrays + scan-free CSR offset allocation (disjoint ranges via atomic)
__global__ void alloc_all_kernel() {
    int i = blockIdx.x * blockDim.x + threadIdx.x;
    if (i < N_SVC) {
        g_rss_svc[i] = rsqrtf((float)max(g_cs_svc[i], 1));
        int c = g_cd_svc[i];
        g_rsd_svc[i] = rsqrtf((float)max(c, 1));
        int o = atomicAdd(&g_tot[0], c);
        g_off_svc[i] = o;
        g_cur_svc[i] = o;
    }
    if (i < N_NODE) {
        g_rss_np[i] = rsqrtf((float)max(g_cs_np[i], 1));
        int c = g_cd_pn[i];
        g_rsd_pn[i] = rsqrtf((float)max(c, 1));
        int o = atomicAdd(&g_tot[1], c);
        g_off_pn[i] = o;
        g_cur_pn[i] = o;
    }
    if (i < N_POD) {
        g_rss_pn[i] = rsqrtf((float)max(g_cs_pn[i], 1));
        int c = g_cd_np[i];
        g_rsd_np[i] = rsqrtf((float)max(c, 1));
        int o = atomicAdd(&g_tot[2], c);
        g_off_np[i] = o;
        g_cur_np[i] = o;
    }
}

// launch 2: bin edges by dst
__global__ void bin_all_kernel(const int* __restrict__ ss, const int* __restrict__ sd,
                               const int* __restrict__ ps, const int* __restrict__ pd,
                               const int* __restrict__ ns, const int* __restrict__ nd,
                               int Es, int Ep, int En) {
    int i = blockIdx.x * blockDim.x + threadIdx.x;
    if (i < Es) {
        int p = atomicAdd(g_cur_svc + sd[i], 1);
        g_srt_svc[p] = ss[i];
        return;
    }
    i -= Es;
    if (i < Ep) {
        int p = atomicAdd(g_cur_pn + pd[i], 1);
        g_srt_pn[p] = ps[i];
        return;
    }
    i -= Ep;
    if (i < En) {
        int p = atomicAdd(g_cur_np + nd[i], 1);
        g_srt_np[p] = ns[i];
    }
}

// launches 3-5: warp-per-dst CSR gather-aggregate (dst norm folded into write)
__global__ void gather_kernel(const float* __restrict__ x, const float* __restrict__ rss,
                              const float* __restrict__ rsd, const int* __restrict__ off,
                              const int* __restrict__ cnt, const int* __restrict__ srt,
                              float* __restrict__ agg, int n) {
    int g = blockIdx.x * blockDim.x + threadIdx.x;
    int w = g >> 5;
    int lane = g & 31;
    if (w >= n) return;
    int o = __ldg(off + w);
    int c = __ldg(cnt + w);

    float4 acc = make_float4(0.f, 0.f, 0.f, 0.f);
    int j = 0;
    for (; j + 4 <= c; j += 4) {
        int s0 = __ldg(srt + o + j);
        int s1 = __ldg(srt + o + j + 1);
        int s2 = __ldg(srt + o + j + 2);
        int s3 = __ldg(srt + o + j + 3);
        float4 v0 = __ldg((const float4*)(x + (size_t)s0 * FDIM) + lane);
        float4 v1 = __ldg((const float4*)(x + (size_t)s1 * FDIM) + lane);
        float4 v2 = __ldg((const float4*)(x + (size_t)s2 * FDIM) + lane);
        float4 v3 = __ldg((const float4*)(x + (size_t)s3 * FDIM) + lane);
        float r0 = __ldg(rss + s0);
        float r1 = __ldg(rss + s1);
        float r2 = __ldg(rss + s2);
        float r3 = __ldg(rss + s3);
        acc.x = fmaf(v0.x, r0, fmaf(v1.x, r1, fmaf(v2.x, r2, fmaf(v3.x, r3, acc.x))));
        acc.y = fmaf(v0.y, r0, fmaf(v1.y, r1, fmaf(v2.y, r2, fmaf(v3.y, r3, acc.y))));
        acc.z = fmaf(v0.z, r0, fmaf(v1.z, r1, fmaf(v2.z, r2, fmaf(v3.z, r3, acc.z))));
        acc.w = fmaf(v0.w, r0, fmaf(v1.w, r1, fmaf(v2.w, r2, fmaf(v3.w, r3, acc.w))));
    }
    for (; j < c; ++j) {
        int s = __ldg(srt + o + j);
        float r = __ldg(rss + s);
        float4 v = __ldg((const float4*)(x + (size_t)s * FDIM) + lane);
        acc.x = fmaf(v.x, r, acc.x);
        acc.y = fmaf(v.y, r, acc.y);
        acc.z = fmaf(v.z, r, acc.z);
        acc.w = fmaf(v.w, r, acc.w);
    }
    float rd = __ldg(rsd + w);
    acc.x *= rd; acc.y *= rd; acc.z *= rd; acc.w *= rd;
    ((float4*)(agg + (size_t)w * FDIM))[lane] = acc;
}

// ---------------- fused GEMM: out = leaky(A@W + b) @ Wl + bl (A pre-normalized) ------
#define SA_LD 132
#define B_SVC_BLKS  ((N_SVC  + 127) / 128)   // 391
#define B_NODE_BLKS ((N_NODE + 127) / 128)   // 157
#define B_POD_BLKS  ((N_POD  + 127) / 128)   // 782

__global__ __launch_bounds__(256, 1)
void fused_all_kernel(const float* __restrict__ agg0, const float* __restrict__ W0,
                      const float* __restrict__ b0, const float* __restrict__ Wl0,
                      const float* __restrict__ bl0,
                      const float* __restrict__ agg1, const float* __restrict__ W1,
                      const float* __restrict__ b1, const float* __restrict__ Wl1,
                      const float* __restrict__ bl1,
                      const float* __restrict__ agg2, const float* __restrict__ W2,
                      const float* __restrict__ b2, const float* __restrict__ Wl2,
                      const float* __restrict__ bl2,
                      float* __restrict__ out_base) {
    extern __shared__ float sm[];
    float* sA  = sm;                         // 128 * 132
    float* sW  = sA + 128 * SA_LD;           // 128 * 128
    float* sWl = sW + 128 * 128;             // 128 * 64
    float* sB  = sWl + 128 * 64;             // 128
    float* sBl = sB + 128;                   // 64

    const int t = threadIdx.x;
    int bid = blockIdx.x;

    const float *agg, *W, *b, *Wl, *bl;
    float* out;
    int nrows, row0;
    if (bid < B_SVC_BLKS) {
        agg = agg0; W = W0; b = b0; Wl = Wl0; bl = bl0;
        out = out_base; nrows = N_SVC; row0 = bid * 128;
    } else if (bid < B_SVC_BLKS + B_NODE_BLKS) {
        agg = agg1; W = W1; b = b1; Wl = Wl1; bl = bl1;
        out = out_base + (size_t)N_SVC * ODIM; nrows = N_NODE;
        row0 = (bid - B_SVC_BLKS) * 128;
    } else {
        agg = agg2; W = W2; b = b2; Wl = Wl2; bl = bl2;
        out = out_base + (size_t)(N_SVC + N_NODE) * ODIM; nrows = N_POD;
        row0 = (bid - B_SVC_BLKS - B_NODE_BLKS) * 128;
    }

    for (int i = t; i < (128 * 128) / 4; i += 256)
        ((float4*)sW)[i] = ((const float4*)W)[i];
    for (int i = t; i < (128 * 64) / 4; i += 256)
        ((float4*)sWl)[i] = ((const float4*)Wl)[i];
    if (t < 128) sB[t] = b[t];
    if (t < 64)  sBl[t] = bl[t];

    for (int i = t; i < 128 * (FDIM / 4); i += 256) {
        int r  = i >> 5;
        int c4 = i & 31;
        float4 v = make_float4(0.f, 0.f, 0.f, 0.f);
        int gr = row0 + r;
        if (gr < nrows)
            v = ((const float4*)(agg + (size_t)gr * FDIM))[c4];
        *((float4*)(sA + r * SA_LD + c4 * 4)) = v;
    }
    __syncthreads();

    const int tcol = t & 15;
    const int trow = t >> 4;
    const int j0 = tcol * 8;
    const int r0 = trow * 8;

    // ---- stage 1: H = A @ W + b ----
    unsigned long long acc[8][4];
    {
        const ulonglong2* pb = (const ulonglong2*)(sB + j0);
        ulonglong2 b01 = pb[0];
        ulonglong2 b23 = pb[1];
        #pragma unroll
        for (int rr = 0; rr < 8; ++rr) {
            acc[rr][0] = b01.x; acc[rr][1] = b01.y;
            acc[rr][2] = b23.x; acc[rr][3] = b23.y;
        }
    }

    #pragma unroll 1
    for (int k0 = 0; k0 < 128; k0 += 4) {
        float4 a4[8];
        #pragma unroll
        for (int rr = 0; rr < 8; ++rr)
            a4[rr] = *(const float4*)(sA + (r0 + rr) * SA_LD + k0);
        #pragma unroll
        for (int kk = 0; kk < 4; ++kk) {
            ulonglong2 w01 = *(const ulonglong2*)(sW + ((k0 + kk) << 7) + j0);
            ulonglong2 w23 = *(const ulonglong2*)(sW + ((k0 + kk) << 7) + j0 + 4);
            #pragma unroll
            for (int rr = 0; rr < 8; ++rr) {
                float a = (&a4[rr].x)[kk];
                unsigned long long aa = pack2(a, a);
                acc[rr][0] = fma2(aa, w01.x, acc[rr][0]);
                acc[rr][1] = fma2(aa, w01.y, acc[rr][1]);
                acc[rr][2] = fma2(aa, w23.x, acc[rr][2]);
                acc[rr][3] = fma2(aa, w23.y, acc[rr][3]);
            }
        }
    }
    __syncthreads();

    // leaky + write H back into sA
    #pragma unroll
    for (int rr = 0; rr < 8; ++rr) {
        float h[8];
        unpack2(acc[rr][0], h[0], h[1]);
        unpack2(acc[rr][1], h[2], h[3]);
        unpack2(acc[rr][2], h[4], h[5]);
        unpack2(acc[rr][3], h[6], h[7]);
        #pragma unroll
        for (int q = 0; q < 8; ++q) h[q] = h[q] > 0.f ? h[q] : 0.01f * h[q];
        *((float4*)(sA + (r0 + rr) * SA_LD + j0))     = make_float4(h[0], h[1], h[2], h[3]);
        *((float4*)(sA + (r0 + rr) * SA_LD + j0 + 4)) = make_float4(h[4], h[5], h[6], h[7]);
    }
    __syncthreads();

    // ---- stage 2: out = H @ Wl + bl ----
    const int oc0 = tcol * 4;
    unsigned long long acc2[8][2];
    {
        ulonglong2 bl2 = *(const ulonglong2*)(sBl + oc0);
        #pragma unroll
        for (int rr = 0; rr < 8; ++rr) { acc2[rr][0] = bl2.x; acc2[rr][1] = bl2.y; }
    }

    #pragma unroll 1
    for (int k0 = 0; k0 < 128; k0 += 4) {
        float4 h4[8];
        #pragma unroll
        for (int rr = 0; rr < 8; ++rr)
            h4[rr] = *(const float4*)(sA + (r0 + rr) * SA_LD + k0);
        #pragma unroll
        for (int kk = 0; kk < 4; ++kk) {
            ulonglong2 wl = *(const ulonglong2*)(sWl + ((k0 + kk) << 6) + oc0);
            #pragma unroll
            for (int rr = 0; rr < 8; ++rr) {
                float h = (&h4[rr].x)[kk];
                unsigned long long hh = pack2(h, h);
                acc2[rr][0] = fma2(hh, wl.x, acc2[rr][0]);
                acc2[rr][1] = fma2(hh, wl.y, acc2[rr][1]);
            }
        }
    }

    #pragma unroll
    for (int rr = 0; rr < 8; ++rr) {
        int gr = row0 + r0 + rr;
        if (gr < nrows) {
            float o[4];
            unpack2(acc2[rr][0], o[0], o[1]);
            unpack2(acc2[rr][1], o[2], o[3]);
            *((float4*)(out + (size_t)gr * ODIM + oc0)) =
                make_float4(o[0], o[1], o[2], o[3]);
        }
    }
}

// trailing cleanup: re-zero counters/totals so next call starts clean
__global__ void cleanup_kernel() {
    const size_t T = (size_t)gridDim.x * blockDim.x;
    const size_t i0 = (size_t)blockIdx.x * blockDim.x + threadIdx.x;
    for (size_t i = i0; i < N_SVC;  i += T) { g_cs_svc[i] = 0; g_cd_svc[i] = 0; }
    for (size_t i = i0; i < N_POD;  i += T) { g_cs_pn[i]  = 0; g_cd_np[i]  = 0; }
    for (size_t i = i0; i < N_NODE; i += T) { g_cd_pn[i]  = 0; g_cs_np[i]  = 0; }
    if (i0 < 3) g_tot[i0] = 0;
}

// ---------------- host launcher ----------------

static inline int cdiv(long long a, long long b) { return (int)((a + b - 1) / b); }

extern "C" void kernel_launch(void* const* d_in, const int* in_sizes, int n_in,
                              void* d_out, int out_size) {
    const float* x_svc  = (const float*)d_in[0];
    const float* x_pod  = (const float*)d_in[1];
    const float* x_node = (const float*)d_in[2];
    const int* svc_src = (const int*)d_in[3];
    const int* svc_dst = (const int*)d_in[4];
    const int* pn_src  = (const int*)d_in[5];
    const int* pn_dst  = (const int*)d_in[6];
    const int* np_src  = (const int*)d_in[7];
    const int* np_dst  = (const int*)d_in[8];
    const float* W_call = (const float*)d_in[9];
    const float* b_call = (const float*)d_in[10];
    const float* W_in   = (const float*)d_in[11];
    const float* b_in   = (const float*)d_in[12];
    const float* W_ni   = (const float*)d_in[13];
    const float* b_ni   = (const float*)d_in[14];
    const float* W_lin_svc  = (const float*)d_in[15];
    const float* b_lin_svc  = (const float*)d_in[16];
    const float* W_lin_node = (const float*)d_in[17];
    const float* b_lin_node = (const float*)d_in[18];
    const float* W_lin_pod  = (const float*)d_in[19];
    const float* b_lin_pod  = (const float*)d_in[20];
    float* out = (float*)d_out;

    const int E_SVC = in_sizes[3];
    const int E_PN  = in_sizes[5];
    const int E_NP  = in_sizes[7];

    float *agg_svc, *agg_node, *agg_pod;
    float *rss_svc, *rsd_svc, *rss_pn, *rsd_pn, *rss_np, *rsd_np;
    int *off_svc, *off_pn, *off_np, *cd_svc, *cd_pn, *cd_np;
    int *srt_svc, *srt_pn, *srt_np;
    cudaGetSymbolAddress((void**)&agg_svc,  g_agg_svc);
    cudaGetSymbolAddress((void**)&agg_node, g_agg_node);
    cudaGetSymbolAddress((void**)&agg_pod,  g_agg_pod);
    cudaGetSymbolAddress((void**)&rss_svc, g_rss_svc);
    cudaGetSymbolAddress((void**)&rsd_svc, g_rsd_svc);
    cudaGetSymbolAddress((void**)&rss_pn,  g_rss_pn);
    cudaGetSymbolAddress((void**)&rsd_pn,  g_rsd_pn);
    cudaGetSymbolAddress((void**)&rss_np,  g_rss_np);
    cudaGetSymbolAddress((void**)&rsd_np,  g_rsd_np);
    cudaGetSymbolAddress((void**)&off_svc, g_off_svc);
    cudaGetSymbolAddress((void**)&off_pn,  g_off_pn);
    cudaGetSymbolAddress((void**)&off_np,  g_off_np);
    cudaGetSymbolAddress((void**)&cd_svc,  g_cd_svc);
    cudaGetSymbolAddress((void**)&cd_pn,   g_cd_pn);
    cudaGetSymbolAddress((void**)&cd_np,   g_cd_np);
    cudaGetSymbolAddress((void**)&srt_svc, g_srt_svc);
    cudaGetSymbolAddress((void**)&srt_pn,  g_srt_pn);
    cudaGetSymbolAddress((void**)&srt_np,  g_srt_np);

    const int TB = 256;
    const long long E_TOT = (long long)E_SVC + E_PN + E_NP;

    // 0: degree counts
    cnt_all_kernel<<<cdiv(E_TOT, TB), TB>>>(svc_src, svc_dst, pn_src, pn_dst,
                                            np_src, np_dst, E_SVC, E_PN, E_NP);
    // 1: rs arrays + CSR offsets
    alloc_all_kernel<<<cdiv(N_POD, TB), TB>>>();
    // 2: bin edges by dst
    bin_all_kernel<<<cdiv(E_TOT, TB), TB>>>(svc_src, svc_dst, pn_src, pn_dst,
                                            np_src, np_dst, E_SVC, E_PN, E_NP);
    // 3: big svc gather (ncu target), 4-5: small gathers
    gather_kernel<<<cdiv((long long)N_SVC * 32, TB), TB>>>(
        x_svc, rss_svc, rsd_svc, off_svc, cd_svc, srt_svc, agg_svc, N_SVC);
    gather_kernel<<<cdiv((long long)N_NODE * 32, TB), TB>>>(
        x_pod, rss_pn, rsd_pn, off_pn, cd_pn, srt_pn, agg_node, N_NODE);
    gather_kernel<<<cdiv((long long)N_POD * 32, TB), TB>>>(
        x_node, rss_np, rsd_np, off_np, cd_np, srt_np, agg_pod, N_POD);

    // 6: fused GEMM over all three types
    const int SMEM = (128 * SA_LD + 128 * 128 + 128 * 64 + 128 + 64) * (int)sizeof(float);
    cudaFuncSetAttribute(fused_all_kernel, cudaFuncAttributeMaxDynamicSharedMemorySize, SMEM);
    fused_all_kernel<<<B_SVC_BLKS + B_NODE_BLKS + B_POD_BLKS, 256, SMEM>>>(
        agg_svc,  W_call, b_call, W_lin_svc,  b_lin_svc,
        agg_node, W_in,   b_in,   W_lin_node, b_lin_node,
        agg_pod,  W_ni,   b_ni,   W_lin_pod,  b_lin_pod,
        out);

    // 7: reset counters for next call
    cleanup_kernel<<<256, TB>>>();
}

// round 9
// speedup vs baseline: 2.0099x; 1.3607x over previous
#include <cuda_runtime.h>
#include <cuda_bf16.h>
#include <cstdint>

#define N_SVC  50000
#define N_NODE 20000
#define N_POD  100000
#define FDIM   128
#define ODIM   64
#define E_SVC_CAP 1600000
#define E_SM_CAP  100000

// ---------------- scratch (device globals; zero-init at load; re-zeroed by cleanup) ----
__device__ int g_cs_svc[N_SVC];
__device__ int g_cd_svc[N_SVC];
__device__ int g_cs_pn[N_POD];
__device__ int g_cd_pn[N_NODE];
__device__ int g_cs_np[N_NODE];
__device__ int g_cd_np[N_POD];
__device__ int g_tot[3];

__device__ float g_rss_svc[N_SVC];
__device__ float g_rsd_svc[N_SVC];
__device__ float g_rss_pn[N_POD];
__device__ float g_rsd_pn[N_NODE];
__device__ float g_rss_np[N_NODE];
__device__ float g_rsd_np[N_POD];

__device__ int g_off_svc[N_SVC];
__device__ int g_cur_svc[N_SVC];
__device__ int g_srt_svc[E_SVC_CAP];
__device__ int g_off_pn[N_NODE];
__device__ int g_cur_pn[N_NODE];
__device__ int g_srt_pn[E_SM_CAP];
__device__ int g_off_np[N_POD];
__device__ int g_cur_np[N_POD];
__device__ int g_srt_np[E_SM_CAP];

__device__ float g_agg_svc [(size_t)N_SVC  * FDIM];
__device__ float g_agg_node[(size_t)N_NODE * FDIM];
__device__ float g_agg_pod [(size_t)N_POD  * FDIM];

// preconverted weight planes per type, laid out exactly as the smem block:
// [0,34816) WH ; [34816,69632) WL ; [69632,87040) W2H ; [87040,104448) W2L
// planes use row stride 136 bf16 (= 272 B)
#define WP_BYTES 104448
__device__ __align__(16) unsigned char g_wp[3][WP_BYTES];

// ---------------- helpers ----------------
__device__ __forceinline__ uint32_t smem_u32(const void* p) {
    uint32_t a;
    asm("{ .reg .u64 t; cvta.to.shared.u64 t, %1; cvt.u32.u64 %0, t; }"
        : "=r"(a) : "l"(p));
    return a;
}

__device__ __forceinline__ void ldsm4(uint32_t* r, uint32_t a) {
    asm volatile("ldmatrix.sync.aligned.m8n8.x4.shared.b16 {%0,%1,%2,%3}, [%4];"
                 : "=r"(r[0]), "=r"(r[1]), "=r"(r[2]), "=r"(r[3]) : "r"(a));
}
__device__ __forceinline__ void ldsm2(uint32_t* r, uint32_t a) {
    asm volatile("ldmatrix.sync.aligned.m8n8.x2.shared.b16 {%0,%1}, [%2];"
                 : "=r"(r[0]), "=r"(r[1]) : "r"(a));
}
__device__ __forceinline__ void mma_bf16(float* c, const uint32_t* a, const uint32_t* b) {
    asm volatile("mma.sync.aligned.m16n8k16.row.col.f32.bf16.bf16.f32 "
                 "{%0,%1,%2,%3}, {%4,%5,%6,%7}, {%8,%9}, {%0,%1,%2,%3};"
                 : "+f"(c[0]), "+f"(c[1]), "+f"(c[2]), "+f"(c[3])
                 : "r"(a[0]), "r"(a[1]), "r"(a[2]), "r"(a[3]), "r"(b[0]), "r"(b[1]));
}

__device__ __forceinline__ void split_bf16(float v, unsigned short& h, unsigned short& l) {
    __nv_bfloat16 bh = __float2bfloat16_rn(v);
    float r = v - __bfloat162float(bh);
    __nv_bfloat16 bl = __float2bfloat16_rn(r);
    h = __bfloat16_as_ushort(bh);
    l = __bfloat16_as_ushort(bl);
}

#define LDW 136   // bf16 elements per row (272 B, conflict-free for ldmatrix)

// ---------------- build kernels (unchanged from the 446us kernel) ----------------

__global__ void cnt_all_kernel(const int* __restrict__ ss, const int* __restrict__ sd,
                               const int* __restrict__ ps, const int* __restrict__ pd,
                               const int* __restrict__ ns, const int* __restrict__ nd,
                               int Es, int Ep, int En) {
    int i = blockIdx.x * blockDim.x + threadIdx.x;
    if (i < Es) {
        atomicAdd(g_cs_svc + ss[i], 1);
        atomicAdd(g_cd_svc + sd[i], 1);
        return;
    }
    i -= Es;
    if (i < Ep) {
        atomicAdd(g_cs_pn + ps[i], 1);
        atomicAdd(g_cd_pn + pd[i], 1);
        return;
    }
    i -= Ep;
    if (i < En) {
        atomicAdd(g_cs_np + ns[i], 1);
        atomicAdd(g_cd_np + nd[i], 1);
    }
}

__global__ void alloc_all_kernel() {
    int i = blockIdx.x * blockDim.x + threadIdx.x;
    if (i < N_SVC) {
        g_rss_svc[i] = rsqrtf((float)max(g_cs_svc[i], 1));
        int c = g_cd_svc[i];
        g_rsd_svc[i] = rsqrtf((float)max(c, 1));
        int o = atomicAdd(&g_tot[0], c);
        g_off_svc[i] = o;
        g_cur_svc[i] = o;
    }
    if (i < N_NODE) {
        g_rss_np[i] = rsqrtf((float)max(g_cs_np[i], 1));
        int c = g_cd_pn[i];
        g_rsd_pn[i] = rsqrtf((float)max(c, 1));
        int o = atomicAdd(&g_tot[1], c);
        g_off_pn[i] = o;
        g_cur_pn[i] = o;
    }
    if (i < N_POD) {
        g_rss_pn[i] = rsqrtf((float)max(g_cs_pn[i], 1));
        int c = g_cd_np[i];
        g_rsd_np[i] = rsqrtf((float)max(c, 1));
        int o = atomicAdd(&g_tot[2], c);
        g_off_np[i] = o;
        g_cur_np[i] = o;
    }
}

__global__ void bin_all_kernel(const int* __restrict__ ss, const int* __restrict__ sd,
                               const int* __restrict__ ps, const int* __restrict__ pd,
                               const int* __restrict__ ns, const int* __restrict__ nd,
                               int Es, int Ep, int En) {
    int i = blockIdx.x * blockDim.x + threadIdx.x;
    if (i < Es) {
        int p = atomicAdd(g_cur_svc + sd[i], 1);
        g_srt_svc[p] = ss[i];
        return;
    }
    i -= Es;
    if (i < Ep) {
        int p = atomicAdd(g_cur_pn + pd[i], 1);
        g_srt_pn[p] = ps[i];
        return;
    }
    i -= Ep;
    if (i < En) {
        int p = atomicAdd(g_cur_np + nd[i], 1);
        g_srt_np[p] = ns[i];
    }
}

__global__ void gather_kernel(const float* __restrict__ x, const float* __restrict__ rss,
                              const float* __restrict__ rsd, const int* __restrict__ off,
                              const int* __restrict__ cnt, const int* __restrict__ srt,
                              float* __restrict__ agg, int n) {
    int g = blockIdx.x * blockDim.x + threadIdx.x;
    int w = g >> 5;
    int lane = g & 31;
    if (w >= n) return;
    int o = __ldg(off + w);
    int c = __ldg(cnt + w);

    float4 acc = make_float4(0.f, 0.f, 0.f, 0.f);
    int j = 0;
    for (; j + 4 <= c; j += 4) {
        int s0 = __ldg(srt + o + j);
        int s1 = __ldg(srt + o + j + 1);
        int s2 = __ldg(srt + o + j + 2);
        int s3 = __ldg(srt + o + j + 3);
        float4 v0 = __ldg((const float4*)(x + (size_t)s0 * FDIM) + lane);
        float4 v1 = __ldg((const float4*)(x + (size_t)s1 * FDIM) + lane);
        float4 v2 = __ldg((const float4*)(x + (size_t)s2 * FDIM) + lane);
        float4 v3 = __ldg((const float4*)(x + (size_t)s3 * FDIM) + lane);
        float r0 = __ldg(rss + s0);
        float r1 = __ldg(rss + s1);
        float r2 = __ldg(rss + s2);
        float r3 = __ldg(rss + s3);
        acc.x = fmaf(v0.x, r0, fmaf(v1.x, r1, fmaf(v2.x, r2, fmaf(v3.x, r3, acc.x))));
        acc.y = fmaf(v0.y, r0, fmaf(v1.y, r1, fmaf(v2.y, r2, fmaf(v3.y, r3, acc.y))));
        acc.z = fmaf(v0.z, r0, fmaf(v1.z, r1, fmaf(v2.z, r2, fmaf(v3.z, r3, acc.z))));
        acc.w = fmaf(v0.w, r0, fmaf(v1.w, r1, fmaf(v2.w, r2, fmaf(v3.w, r3, acc.w))));
    }
    for (; j < c; ++j) {
        int s = __ldg(srt + o + j);
        float r = __ldg(rss + s);
        float4 v = __ldg((const float4*)(x + (size_t)s * FDIM) + lane);
        acc.x = fmaf(v.x, r, acc.x);
        acc.y = fmaf(v.y, r, acc.y);
        acc.z = fmaf(v.z, r, acc.z);
        acc.w = fmaf(v.w, r, acc.w);
    }
    float rd = __ldg(rsd + w);
    acc.x *= rd; acc.y *= rd; acc.z *= rd; acc.w *= rd;
    ((float4*)(agg + (size_t)w * FDIM))[lane] = acc;
}

// ---------------- weight prep: transpose + bf16 split into padded planes ----------
__global__ void wprep_kernel(const float* __restrict__ W0, const float* __restrict__ Wl0,
                             const float* __restrict__ W1, const float* __restrict__ Wl1,
                             const float* __restrict__ W2, const float* __restrict__ Wl2) {
    int tid = blockIdx.x * blockDim.x + threadIdx.x;
    if (tid >= 3 * 12288) return;
    int type = tid / 12288;
    int r = tid % 12288;
    const float* W  = (type == 0) ? W0 : (type == 1) ? W1 : W2;
    const float* Wl = (type == 0) ? Wl0 : (type == 1) ? Wl1 : Wl2;
    unsigned char* base = g_wp[type];

    if (r < 8192) {
        // stage1 B^T[n][k]: n in [0,128), k pair
        int n = r & 127, k = (r >> 7) * 2;
        float w0 = W[k * 128 + n];
        float w1 = W[(k + 1) * 128 + n];
        unsigned short h0, l0, h1, l1;
        split_bf16(w0, h0, l0);
        split_bf16(w1, h1, l1);
        uint32_t o = (uint32_t)(n * LDW + k) * 2;
        *(uint32_t*)(base + 0     + o) = (uint32_t)h0 | ((uint32_t)h1 << 16);
        *(uint32_t*)(base + 34816 + o) = (uint32_t)l0 | ((uint32_t)l1 << 16);
    } else {
        // stage2 B^T[n][k]: n in [0,64)
        int r2 = r - 8192;
        int n = r2 & 63, k = (r2 >> 6) * 2;
        float w0 = Wl[k * 64 + n];
        float w1 = Wl[(k + 1) * 64 + n];
        unsigned short h0, l0, h1, l1;
        split_bf16(w0, h0, l0);
        split_bf16(w1, h1, l1);
        uint32_t o = (uint32_t)(n * LDW + k) * 2;
        *(uint32_t*)(base + 69632 + o) = (uint32_t)h0 | ((uint32_t)h1 << 16);
        *(uint32_t*)(base + 87040 + o) = (uint32_t)l0 | ((uint32_t)l1 << 16);
    }
}

// ---------------- fused mma.sync GEMM: out = leaky(A@W + b) @ Wl + bl --------------
#define B_SVC_BLKS  ((N_SVC  + 127) / 128)   // 391
#define B_NODE_BLKS ((N_NODE + 127) / 128)   // 157
#define B_POD_BLKS  ((N_POD  + 127) / 128)   // 782

// smem byte layout
#define SMM_B1   0                     // 128 f32
#define SMM_B2   512                   // 64 f32
#define SMM_AH   768                   // 128 x LDW bf16 = 34816 B
#define SMM_AL   (SMM_AH + 34816)
#define SMM_WH   (SMM_AL + 34816)      // weight block, contiguous, = g_wp layout
#define SMM_WL   (SMM_WH + 34816)
#define SMM_W2H  (SMM_WL + 34816)
#define SMM_W2L  (SMM_W2H + 17408)
#define SMM_TOTAL (SMM_W2L + 17408)    // 175616

__global__ __launch_bounds__(256, 1)
void fused_mma_kernel(const float* __restrict__ agg0, const float* __restrict__ b0,
                      const float* __restrict__ bl0,
                      const float* __restrict__ agg1, const float* __restrict__ b1,
                      const float* __restrict__ bl1,
                      const float* __restrict__ agg2, const float* __restrict__ b2,
                      const float* __restrict__ bl2,
                      float* __restrict__ out_base) {
    extern __shared__ char smem[];
    const uint32_t sb = smem_u32(smem);
    const int t = threadIdx.x;
    const int wid = t >> 5;
    const int l = t & 31;

    int bid = blockIdx.x;
    const float *agg, *bias1, *bias2;
    const unsigned char* wp;
    float* out;
    int nrows, row0;
    if (bid < B_SVC_BLKS) {
        agg = agg0; bias1 = b0; bias2 = bl0; wp = g_wp[0];
        out = out_base; nrows = N_SVC; row0 = bid * 128;
    } else if (bid < B_SVC_BLKS + B_NODE_BLKS) {
        agg = agg1; bias1 = b1; bias2 = bl1; wp = g_wp[1];
        out = out_base + (size_t)N_SVC * ODIM; nrows = N_NODE;
        row0 = (bid - B_SVC_BLKS) * 128;
    } else {
        agg = agg2; bias1 = b2; bias2 = bl2; wp = g_wp[2];
        out = out_base + (size_t)(N_SVC + N_NODE) * ODIM; nrows = N_POD;
        row0 = (bid - B_SVC_BLKS - B_NODE_BLKS) * 128;
    }

    float* fB1 = (float*)(smem + SMM_B1);
    float* fB2 = (float*)(smem + SMM_B2);
    if (t < 128) fB1[t] = bias1[t];
    if (t < 64)  fB2[t] = bias2[t];

    // weights: one contiguous copy (layout matches g_wp)
    {
        const uint4* src = (const uint4*)wp;
        uint4* dst = (uint4*)(smem + SMM_WH);
        for (int i = t; i < WP_BYTES / 16; i += 256) dst[i] = src[i];
    }

    // A tile: fp32 load, bf16 hi/lo split, padded-row store
    for (int i4 = t; i4 < 4096; i4 += 256) {
        int r = i4 >> 5;
        int c4 = i4 & 31;
        int k0 = c4 * 4;
        float4 v = make_float4(0.f, 0.f, 0.f, 0.f);
        int gr = row0 + r;
        if (gr < nrows) v = ((const float4*)(agg + (size_t)gr * FDIM))[c4];
        unsigned short hx, lx, hy, ly, hz, lz, hw, lw;
        split_bf16(v.x, hx, lx);
        split_bf16(v.y, hy, ly);
        split_bf16(v.z, hz, lz);
        split_bf16(v.w, hw, lw);
        uint32_t o = (uint32_t)(r * LDW + k0) * 2;
        uint2 hv = make_uint2((uint32_t)hx | ((uint32_t)hy << 16),
                              (uint32_t)hz | ((uint32_t)hw << 16));
        uint2 lv = make_uint2((uint32_t)lx | ((uint32_t)ly << 16),
                              (uint32_t)lz | ((uint32_t)lw << 16));
        *(uint2*)(smem + SMM_AH + o) = hv;
        *(uint2*)(smem + SMM_AL + o) = lv;
    }
    __syncthreads();

    const int m0 = wid * 16;    // private 16-row stripe per warp
    // ldmatrix lane-address offsets (bytes)
    const uint32_t aoff = (uint32_t)((m0 + (l & 15)) * LDW + ((l >> 4) * 8)) * 2;
    const uint32_t boff = (uint32_t)(((l & 7)) * LDW + (((l >> 3) & 1) * 8)) * 2;

    // ---- stage 1: C1[16x128] = A @ W + b (bf16 3-product split) ----
    float acc[16][4];
    {
        #pragma unroll
        for (int nt = 0; nt < 16; ++nt) {
            int col = nt * 8 + 2 * (l & 3);
            float bA = fB1[col], bB = fB1[col + 1];
            acc[nt][0] = bA; acc[nt][1] = bB;
            acc[nt][2] = bA; acc[nt][3] = bB;
        }
    }
    #pragma unroll 1
    for (int kk = 0; kk < 8; ++kk) {
        uint32_t ah[4], al[4];
        ldsm4(ah, sb + SMM_AH + aoff + kk * 32);
        ldsm4(al, sb + SMM_AL + aoff + kk * 32);
        #pragma unroll
        for (int nt = 0; nt < 16; ++nt) {
            uint32_t bh[2], bl_[2];
            uint32_t bb = boff + nt * (8 * LDW * 2) + kk * 32;
            ldsm2(bh,  sb + SMM_WH + bb);
            ldsm2(bl_, sb + SMM_WL + bb);
            mma_bf16(acc[nt], ah, bh);
            mma_bf16(acc[nt], al, bh);
            mma_bf16(acc[nt], ah, bl_);
        }
    }

    // ---- epilogue 1: H = leaky(C1), split back into AH/AL (same warp's stripe) ----
    {
        int r1 = m0 + (l >> 2);
        int r2 = r1 + 8;
        #pragma unroll
        for (int nt = 0; nt < 16; ++nt) {
            int col = nt * 8 + 2 * (l & 3);
            float v0 = acc[nt][0], v1 = acc[nt][1];
            float v2 = acc[nt][2], v3 = acc[nt][3];
            v0 = v0 > 0.f ? v0 : 0.01f * v0;
            v1 = v1 > 0.f ? v1 : 0.01f * v1;
            v2 = v2 > 0.f ? v2 : 0.01f * v2;
            v3 = v3 > 0.f ? v3 : 0.01f * v3;
            unsigned short h0, l0, h1, l1, h2, l2, h3, l3;
            split_bf16(v0, h0, l0);
            split_bf16(v1, h1, l1);
            split_bf16(v2, h2, l2);
            split_bf16(v3, h3, l3);
            uint32_t o1 = (uint32_t)(r1 * LDW + col) * 2;
            uint32_t o2 = (uint32_t)(r2 * LDW + col) * 2;
            *(uint32_t*)(smem + SMM_AH + o1) = (uint32_t)h0 | ((uint32_t)h1 << 16);
            *(uint32_t*)(smem + SMM_AL + o1) = (uint32_t)l0 | ((uint32_t)l1 << 16);
            *(uint32_t*)(smem + SMM_AH + o2) = (uint32_t)h2 | ((uint32_t)h3 << 16);
            *(uint32_t*)(smem + SMM_AL + o2) = (uint32_t)l2 | ((uint32_t)l3 << 16);
        }
    }
    __syncwarp();

    // ---- stage 2: C2[16x64] = H @ Wl + bl ----
    float acc2[8][4];
    {
        #pragma unroll
        for (int nt = 0; nt < 8; ++nt) {
            int col = nt * 8 + 2 * (l & 3);
            float bA = fB2[col], bB = fB2[col + 1];
            acc2[nt][0] = bA; acc2[nt][1] = bB;
            acc2[nt][2] = bA; acc2[nt][3] = bB;
        }
    }
    #pragma unroll 1
    for (int kk = 0; kk < 8; ++kk) {
        uint32_t ah[4], al[4];
        ldsm4(ah, sb + SMM_AH + aoff + kk * 32);
        ldsm4(al, sb + SMM_AL + aoff + kk * 32);
        #pragma unroll
        for (int nt = 0; nt < 8; ++nt) {
            uint32_t bh[2], bl_[2];
            uint32_t bb = boff + nt * (8 * LDW * 2) + kk * 32;
            ldsm2(bh,  sb + SMM_W2H + bb);
            ldsm2(bl_, sb + SMM_W2L + bb);
            mma_bf16(acc2[nt], ah, bh);
            mma_bf16(acc2[nt], al, bh);
            mma_bf16(acc2[nt], ah, bl_);
        }
    }

    // ---- epilogue 2: write out ----
    {
        int r1 = row0 + m0 + (l >> 2);
        int r2 = r1 + 8;
        #pragma unroll
        for (int nt = 0; nt < 8; ++nt) {
            int col = nt * 8 + 2 * (l & 3);
            if (r1 < nrows)
                *(float2*)(out + (size_t)r1 * ODIM + col) =
                    make_float2(acc2[nt][0], acc2[nt][1]);
            if (r2 < nrows)
                *(float2*)(out + (size_t)r2 * ODIM + col) =
                    make_float2(acc2[nt][2], acc2[nt][3]);
        }
    }
}

// trailing cleanup: re-zero counters/totals so next call starts clean
__global__ void cleanup_kernel() {
    const size_t T = (size_t)gridDim.x * blockDim.x;
    const size_t i0 = (size_t)blockIdx.x * blockDim.x + threadIdx.x;
    for (size_t i = i0; i < N_SVC;  i += T) { g_cs_svc[i] = 0; g_cd_svc[i] = 0; }
    for (size_t i = i0; i < N_POD;  i += T) { g_cs_pn[i]  = 0; g_cd_np[i]  = 0; }
    for (size_t i = i0; i < N_NODE; i += T) { g_cd_pn[i]  = 0; g_cs_np[i]  = 0; }
    if (i0 < 3) g_tot[i0] = 0;
}

// ---------------- host launcher ----------------

static inline int cdiv(long long a, long long b) { return (int)((a + b - 1) / b); }

extern "C" void kernel_launch(void* const* d_in, const int* in_sizes, int n_in,
                              void* d_out, int out_size) {
    const float* x_svc  = (const float*)d_in[0];
    const float* x_pod  = (const float*)d_in[1];
    const float* x_node = (const float*)d_in[2];
    const int* svc_src = (const int*)d_in[3];
    const int* svc_dst = (const int*)d_in[4];
    const int* pn_src  = (const int*)d_in[5];
    const int* pn_dst  = (const int*)d_in[6];
    const int* np_src  = (const int*)d_in[7];
    const int* np_dst  = (const int*)d_in[8];
    const float* W_call = (const float*)d_in[9];
    const float* b_call = (const float*)d_in[10];
    const float* W_in   = (const float*)d_in[11];
    const float* b_in   = (const float*)d_in[12];
    const float* W_ni   = (const float*)d_in[13];
    const float* b_ni   = (const float*)d_in[14];
    const float* W_lin_svc  = (const float*)d_in[15];
    const float* b_lin_svc  = (const float*)d_in[16];
    const float* W_lin_node = (const float*)d_in[17];
    const float* b_lin_node = (const float*)d_in[18];
    const float* W_lin_pod  = (const float*)d_in[19];
    const float* b_lin_pod  = (const float*)d_in[20];
    float* out = (float*)d_out;

    const int E_SVC = in_sizes[3];
    const int E_PN  = in_sizes[5];
    const int E_NP  = in_sizes[7];

    float *agg_svc, *agg_node, *agg_pod;
    float *rss_svc, *rsd_svc, *rss_pn, *rsd_pn, *rss_np, *rsd_np;
    int *off_svc, *off_pn, *off_np, *cd_svc, *cd_pn, *cd_np;
    int *srt_svc, *srt_pn, *srt_np;
    cudaGetSymbolAddress((void**)&agg_svc,  g_agg_svc);
    cudaGetSymbolAddress((void**)&agg_node, g_agg_node);
    cudaGetSymbolAddress((void**)&agg_pod,  g_agg_pod);
    cudaGetSymbolAddress((void**)&rss_svc, g_rss_svc);
    cudaGetSymbolAddress((void**)&rsd_svc, g_rsd_svc);
    cudaGetSymbolAddress((void**)&rss_pn,  g_rss_pn);
    cudaGetSymbolAddress((void**)&rsd_pn,  g_rsd_pn);
    cudaGetSymbolAddress((void**)&rss_np,  g_rss_np);
    cudaGetSymbolAddress((void**)&rsd_np,  g_rsd_np);
    cudaGetSymbolAddress((void**)&off_svc, g_off_svc);
    cudaGetSymbolAddress((void**)&off_pn,  g_off_pn);
    cudaGetSymbolAddress((void**)&off_np,  g_off_np);
    cudaGetSymbolAddress((void**)&cd_svc,  g_cd_svc);
    cudaGetSymbolAddress((void**)&cd_pn,   g_cd_pn);
    cudaGetSymbolAddress((void**)&cd_np,   g_cd_np);
    cudaGetSymbolAddress((void**)&srt_svc, g_srt_svc);
    cudaGetSymbolAddress((void**)&srt_pn,  g_srt_pn);
    cudaGetSymbolAddress((void**)&srt_np,  g_srt_np);

    const int TB = 256;
    const long long E_TOT = (long long)E_SVC + E_PN + E_NP;

    // 0: degree counts
    cnt_all_kernel<<<cdiv(E_TOT, TB), TB>>>(svc_src, svc_dst, pn_src, pn_dst,
                                            np_src, np_dst, E_SVC, E_PN, E_NP);
    // 1: rs arrays + CSR offsets
    alloc_all_kernel<<<cdiv(N_POD, TB), TB>>>();
    // 2: bin edges by dst
    bin_all_kernel<<<cdiv(E_TOT, TB), TB>>>(svc_src, svc_dst, pn_src, pn_dst,
                                            np_src, np_dst, E_SVC, E_PN, E_NP);
    // 3: big svc gather (ncu capture slot — control), 4-5: small gathers
    gather_kernel<<<cdiv((long long)N_SVC * 32, TB), TB>>>(
        x_svc, rss_svc, rsd_svc, off_svc, cd_svc, srt_svc, agg_svc, N_SVC);
    gather_kernel<<<cdiv((long long)N_NODE * 32, TB), TB>>>(
        x_pod, rss_pn, rsd_pn, off_pn, cd_pn, srt_pn, agg_node, N_NODE);
    gather_kernel<<<cdiv((long long)N_POD * 32, TB), TB>>>(
        x_node, rss_np, rsd_np, off_np, cd_np, srt_np, agg_pod, N_POD);

    // 6: weight prep (transpose + bf16 split into padded planes)
    wprep_kernel<<<cdiv(3 * 12288, TB), TB>>>(W_call, W_lin_svc,
                                              W_in,   W_lin_node,
                                              W_ni,   W_lin_pod);

    // 7: fused mma.sync GEMM over all three types
    cudaFuncSetAttribute(fused_mma_kernel, cudaFuncAttributeMaxDynamicSharedMemorySize,
                         SMM_TOTAL);
    fused_mma_kernel<<<B_SVC_BLKS + B_NODE_BLKS + B_POD_BLKS, 256, SMM_TOTAL>>>(
        agg_svc,  b_call, b_lin_svc,
        agg_node, b_in,   b_lin_node,
        agg_pod,  b_ni,   b_lin_pod,
        out);

    // 8: reset counters for next call
    cleanup_kernel<<<256, TB>>>();
}

// round 10
// speedup vs baseline: 2.1141x; 1.0518x over previous
#include <cuda_runtime.h>
#include <cuda_bf16.h>
#include <cstdint>

#define N_SVC  50000
#define N_NODE 20000
#define N_POD  100000
#define FDIM   128
#define ODIM   64
#define E_SVC_CAP 1600000
#define E_SM_CAP  100000

// ---------------- scratch (device globals; zero-init at load; re-zeroed by cleanup) ----
__device__ int g_cs_svc[N_SVC];
__device__ int g_cd_svc[N_SVC];
__device__ int g_cs_pn[N_POD];
__device__ int g_cd_pn[N_NODE];
__device__ int g_cs_np[N_NODE];
__device__ int g_cd_np[N_POD];
__device__ int g_tot[3];

__device__ float g_rss_svc[N_SVC];
__device__ float g_rsd_svc[N_SVC];
__device__ float g_rss_pn[N_POD];
__device__ float g_rsd_pn[N_NODE];
__device__ float g_rss_np[N_NODE];
__device__ float g_rsd_np[N_POD];

__device__ int g_off_svc[N_SVC];
__device__ int g_cur_svc[N_SVC];
__device__ int g_srt_svc[E_SVC_CAP];
__device__ int g_off_pn[N_NODE];
__device__ int g_cur_pn[N_NODE];
__device__ int g_srt_pn[E_SM_CAP];
__device__ int g_off_np[N_POD];
__device__ int g_cur_np[N_POD];
__device__ int g_srt_np[E_SM_CAP];

__device__ float g_agg_svc [(size_t)N_SVC  * FDIM];
__device__ float g_agg_node[(size_t)N_NODE * FDIM];
__device__ float g_agg_pod [(size_t)N_POD  * FDIM];

// preconverted weight planes per type (layout = smem block), row stride 136 bf16
#define WP_BYTES 104448
__device__ __align__(16) unsigned char g_wp[3][WP_BYTES];

// ---------------- helpers ----------------
__device__ __forceinline__ uint32_t smem_u32(const void* p) {
    uint32_t a;
    asm("{ .reg .u64 t; cvta.to.shared.u64 t, %1; cvt.u32.u64 %0, t; }"
        : "=r"(a) : "l"(p));
    return a;
}
__device__ __forceinline__ void ldsm4(uint32_t* r, uint32_t a) {
    asm volatile("ldmatrix.sync.aligned.m8n8.x4.shared.b16 {%0,%1,%2,%3}, [%4];"
                 : "=r"(r[0]), "=r"(r[1]), "=r"(r[2]), "=r"(r[3]) : "r"(a));
}
__device__ __forceinline__ void ldsm2(uint32_t* r, uint32_t a) {
    asm volatile("ldmatrix.sync.aligned.m8n8.x2.shared.b16 {%0,%1}, [%2];"
                 : "=r"(r[0]), "=r"(r[1]) : "r"(a));
}
__device__ __forceinline__ void mma_bf16(float* c, const uint32_t* a, const uint32_t* b) {
    asm volatile("mma.sync.aligned.m16n8k16.row.col.f32.bf16.bf16.f32 "
                 "{%0,%1,%2,%3}, {%4,%5,%6,%7}, {%8,%9}, {%0,%1,%2,%3};"
                 : "+f"(c[0]), "+f"(c[1]), "+f"(c[2]), "+f"(c[3])
                 : "r"(a[0]), "r"(a[1]), "r"(a[2]), "r"(a[3]), "r"(b[0]), "r"(b[1]));
}
__device__ __forceinline__ void split_bf16(float v, unsigned short& h, unsigned short& l) {
    __nv_bfloat16 bh = __float2bfloat16_rn(v);
    float r = v - __bfloat162float(bh);
    __nv_bfloat16 bl = __float2bfloat16_rn(r);
    h = __bfloat16_as_ushort(bh);
    l = __bfloat16_as_ushort(bl);
}

#define LDW 136   // bf16 elements per row (272 B, conflict-free for ldmatrix)

// ---------------- weight prep (launch 0) ----------------
__global__ void wprep_kernel(const float* __restrict__ W0, const float* __restrict__ Wl0,
                             const float* __restrict__ W1, const float* __restrict__ Wl1,
                             const float* __restrict__ W2, const float* __restrict__ Wl2) {
    int tid = blockIdx.x * blockDim.x + threadIdx.x;
    if (tid >= 3 * 12288) return;
    int type = tid / 12288;
    int r = tid % 12288;
    const float* W  = (type == 0) ? W0 : (type == 1) ? W1 : W2;
    const float* Wl = (type == 0) ? Wl0 : (type == 1) ? Wl1 : Wl2;
    unsigned char* base = g_wp[type];

    if (r < 8192) {
        int n = r & 127, k = (r >> 7) * 2;
        float w0 = W[k * 128 + n];
        float w1 = W[(k + 1) * 128 + n];
        unsigned short h0, l0, h1, l1;
        split_bf16(w0, h0, l0);
        split_bf16(w1, h1, l1);
        uint32_t o = (uint32_t)(n * LDW + k) * 2;
        *(uint32_t*)(base + 0     + o) = (uint32_t)h0 | ((uint32_t)h1 << 16);
        *(uint32_t*)(base + 34816 + o) = (uint32_t)l0 | ((uint32_t)l1 << 16);
    } else {
        int r2 = r - 8192;
        int n = r2 & 63, k = (r2 >> 6) * 2;
        float w0 = Wl[k * 64 + n];
        float w1 = Wl[(k + 1) * 64 + n];
        unsigned short h0, l0, h1, l1;
        split_bf16(w0, h0, l0);
        split_bf16(w1, h1, l1);
        uint32_t o = (uint32_t)(n * LDW + k) * 2;
        *(uint32_t*)(base + 69632 + o) = (uint32_t)h0 | ((uint32_t)h1 << 16);
        *(uint32_t*)(base + 87040 + o) = (uint32_t)l0 | ((uint32_t)l1 << 16);
    }
}

// ---------------- cnt (launch 1): 4 edges/thread, vector loads ----------------
__device__ __forceinline__ void cnt_seg(const int* __restrict__ src,
                                        const int* __restrict__ dst,
                                        int E, int q, int* __restrict__ cs,
                                        int* __restrict__ cd) {
    int e0 = q * 4;
    if (e0 + 4 <= E) {
        int4 s = __ldg((const int4*)(src + e0));
        int4 d = __ldg((const int4*)(dst + e0));
        atomicAdd(cs + s.x, 1); atomicAdd(cs + s.y, 1);
        atomicAdd(cs + s.z, 1); atomicAdd(cs + s.w, 1);
        atomicAdd(cd + d.x, 1); atomicAdd(cd + d.y, 1);
        atomicAdd(cd + d.z, 1); atomicAdd(cd + d.w, 1);
    } else {
        for (int e = e0; e < E; ++e) {
            atomicAdd(cs + __ldg(src + e), 1);
            atomicAdd(cd + __ldg(dst + e), 1);
        }
    }
}

__global__ void cnt_all_kernel(const int* __restrict__ ss, const int* __restrict__ sd,
                               const int* __restrict__ ps, const int* __restrict__ pd,
                               const int* __restrict__ ns, const int* __restrict__ nd,
                               int Es, int Ep, int En) {
    int q = blockIdx.x * blockDim.x + threadIdx.x;
    int Qs = (Es + 3) >> 2, Qp = (Ep + 3) >> 2, Qn = (En + 3) >> 2;
    if (q < Qs) { cnt_seg(ss, sd, Es, q, g_cs_svc, g_cd_svc); return; }
    q -= Qs;
    if (q < Qp) { cnt_seg(ps, pd, Ep, q, g_cs_pn, g_cd_pn); return; }
    q -= Qp;
    if (q < Qn) { cnt_seg(ns, nd, En, q, g_cs_np, g_cd_np); }
}

// ---------------- alloc (launch 2): warp-aggregated offset allocation -----------
__device__ __forceinline__ int warp_alloc(int c, int lane, int* tot) {
    int pre = c;
    #pragma unroll
    for (int d = 1; d < 32; d <<= 1) {
        int v = __shfl_up_sync(0xffffffffu, pre, d);
        if (lane >= d) pre += v;
    }
    int wtot = __shfl_sync(0xffffffffu, pre, 31);
    int base = 0;
    if (lane == 31) base = atomicAdd(tot, wtot);
    base = __shfl_sync(0xffffffffu, base, 31);
    return base + pre - c;
}

__global__ void alloc_all_kernel() {
    int i = blockIdx.x * blockDim.x + threadIdx.x;
    int lane = threadIdx.x & 31;
    {
        int c = 0;
        if (i < N_SVC) {
            g_rss_svc[i] = rsqrtf((float)max(g_cs_svc[i], 1));
            c = g_cd_svc[i];
            g_rsd_svc[i] = rsqrtf((float)max(c, 1));
        }
        int o = warp_alloc(c, lane, &g_tot[0]);
        if (i < N_SVC) { g_off_svc[i] = o; g_cur_svc[i] = o; }
    }
    {
        int c = 0;
        if (i < N_NODE) {
            g_rss_np[i] = rsqrtf((float)max(g_cs_np[i], 1));
            c = g_cd_pn[i];
            g_rsd_pn[i] = rsqrtf((float)max(c, 1));
        }
        int o = warp_alloc(c, lane, &g_tot[1]);
        if (i < N_NODE) { g_off_pn[i] = o; g_cur_pn[i] = o; }
    }
    {
        int c = 0;
        if (i < N_POD) {
            g_rss_pn[i] = rsqrtf((float)max(g_cs_pn[i], 1));
            c = g_cd_np[i];
            g_rsd_np[i] = rsqrtf((float)max(c, 1));
        }
        int o = warp_alloc(c, lane, &g_tot[2]);
        if (i < N_POD) { g_off_np[i] = o; g_cur_np[i] = o; }
    }
}

// ---------------- bin (launch 3, ncu capture target): 4 edges/thread -----------
__device__ __forceinline__ void bin_seg(const int* __restrict__ src,
                                        const int* __restrict__ dst,
                                        int E, int q, int* __restrict__ cur,
                                        int* __restrict__ srt) {
    int e0 = q * 4;
    if (e0 + 4 <= E) {
        int4 s = __ldg((const int4*)(src + e0));
        int4 d = __ldg((const int4*)(dst + e0));
        srt[atomicAdd(cur + d.x, 1)] = s.x;
        srt[atomicAdd(cur + d.y, 1)] = s.y;
        srt[atomicAdd(cur + d.z, 1)] = s.z;
        srt[atomicAdd(cur + d.w, 1)] = s.w;
    } else {
        for (int e = e0; e < E; ++e)
            srt[atomicAdd(cur + __ldg(dst + e), 1)] = __ldg(src + e);
    }
}

__global__ void bin_all_kernel(const int* __restrict__ ss, const int* __restrict__ sd,
                               const int* __restrict__ ps, const int* __restrict__ pd,
                               const int* __restrict__ ns, const int* __restrict__ nd,
                               int Es, int Ep, int En) {
    int q = blockIdx.x * blockDim.x + threadIdx.x;
    int Qs = (Es + 3) >> 2, Qp = (Ep + 3) >> 2, Qn = (En + 3) >> 2;
    if (q < Qs) { bin_seg(ss, sd, Es, q, g_cur_svc, g_srt_svc); return; }
    q -= Qs;
    if (q < Qp) { bin_seg(ps, pd, Ep, q, g_cur_pn, g_srt_pn); return; }
    q -= Qp;
    if (q < Qn) { bin_seg(ns, nd, En, q, g_cur_np, g_srt_np); }
}

// ---------------- gather (launch 4): all 3 types, warp per dst, 8-deep unroll ----
__device__ __forceinline__ void gather_one(const float* __restrict__ x,
                                           const float* __restrict__ rss,
                                           const float* __restrict__ rsd,
                                           const int* __restrict__ off,
                                           const int* __restrict__ cnt,
                                           const int* __restrict__ srt,
                                           float* __restrict__ agg,
                                           int w, int lane) {
    int o = __ldg(off + w);
    int c = __ldg(cnt + w);

    float4 acc = make_float4(0.f, 0.f, 0.f, 0.f);
    int j = 0;
    for (; j + 8 <= c; j += 8) {
        int s[8];
        #pragma unroll
        for (int u = 0; u < 8; ++u) s[u] = __ldg(srt + o + j + u);
        float4 v[8];
        #pragma unroll
        for (int u = 0; u < 8; ++u)
            v[u] = __ldg((const float4*)(x + (size_t)s[u] * FDIM) + lane);
        float r[8];
        #pragma unroll
        for (int u = 0; u < 8; ++u) r[u] = __ldg(rss + s[u]);
        #pragma unroll
        for (int u = 0; u < 8; ++u) {
            acc.x = fmaf(v[u].x, r[u], acc.x);
            acc.y = fmaf(v[u].y, r[u], acc.y);
            acc.z = fmaf(v[u].z, r[u], acc.z);
            acc.w = fmaf(v[u].w, r[u], acc.w);
        }
    }
    for (; j < c; ++j) {
        int s = __ldg(srt + o + j);
        float r = __ldg(rss + s);
        float4 v = __ldg((const float4*)(x + (size_t)s * FDIM) + lane);
        acc.x = fmaf(v.x, r, acc.x);
        acc.y = fmaf(v.y, r, acc.y);
        acc.z = fmaf(v.z, r, acc.z);
        acc.w = fmaf(v.w, r, acc.w);
    }
    float rd = __ldg(rsd + w);
    acc.x *= rd; acc.y *= rd; acc.z *= rd; acc.w *= rd;
    ((float4*)(agg + (size_t)w * FDIM))[lane] = acc;
}

__global__ void gather_all_kernel(const float* __restrict__ x_svc,
                                  const float* __restrict__ x_pod,
                                  const float* __restrict__ x_node) {
    int g = blockIdx.x * blockDim.x + threadIdx.x;
    int w = g >> 5;
    int lane = g & 31;
    if (w < N_SVC) {
        gather_one(x_svc, g_rss_svc, g_rsd_svc, g_off_svc, g_cd_svc, g_srt_svc,
                   g_agg_svc, w, lane);
        return;
    }
    w -= N_SVC;
    if (w < N_NODE) {
        gather_one(x_pod, g_rss_pn, g_rsd_pn, g_off_pn, g_cd_pn, g_srt_pn,
                   g_agg_node, w, lane);
        return;
    }
    w -= N_NODE;
    if (w < N_POD) {
        gather_one(x_node, g_rss_np, g_rsd_np, g_off_np, g_cd_np, g_srt_np,
                   g_agg_pod, w, lane);
    }
}

// ---------------- fused mma.sync GEMM (launch 5, unchanged) ----------------
#define B_SVC_BLKS  ((N_SVC  + 127) / 128)   // 391
#define B_NODE_BLKS ((N_NODE + 127) / 128)   // 157
#define B_POD_BLKS  ((N_POD  + 127) / 128)   // 782

#define SMM_B1   0
#define SMM_B2   512
#define SMM_AH   768
#define SMM_AL   (SMM_AH + 34816)
#define SMM_WH   (SMM_AL + 34816)
#define SMM_WL   (SMM_WH + 34816)
#define SMM_W2H  (SMM_WL + 34816)
#define SMM_W2L  (SMM_W2H + 17408)
#define SMM_TOTAL (SMM_W2L + 17408)    // 175616

__global__ __launch_bounds__(256, 1)
void fused_mma_kernel(const float* __restrict__ agg0, const float* __restrict__ b0,
                      const float* __restrict__ bl0,
                      const float* __restrict__ agg1, const float* __restrict__ b1,
                      const float* __restrict__ bl1,
                      const float* __restrict__ agg2, const float* __restrict__ b2,
                      const float* __restrict__ bl2,
                      float* __restrict__ out_base) {
    extern __shared__ char smem[];
    const uint32_t sb = smem_u32(smem);
    const int t = threadIdx.x;
    const int wid = t >> 5;
    const int l = t & 31;

    int bid = blockIdx.x;
    const float *agg, *bias1, *bias2;
    const unsigned char* wp;
    float* out;
    int nrows, row0;
    if (bid < B_SVC_BLKS) {
        agg = agg0; bias1 = b0; bias2 = bl0; wp = g_wp[0];
        out = out_base; nrows = N_SVC; row0 = bid * 128;
    } else if (bid < B_SVC_BLKS + B_NODE_BLKS) {
        agg = agg1; bias1 = b1; bias2 = bl1; wp = g_wp[1];
        out = out_base + (size_t)N_SVC * ODIM; nrows = N_NODE;
        row0 = (bid - B_SVC_BLKS) * 128;
    } else {
        agg = agg2; bias1 = b2; bias2 = bl2; wp = g_wp[2];
        out = out_base + (size_t)(N_SVC + N_NODE) * ODIM; nrows = N_POD;
        row0 = (bid - B_SVC_BLKS - B_NODE_BLKS) * 128;
    }

    float* fB1 = (float*)(smem + SMM_B1);
    float* fB2 = (float*)(smem + SMM_B2);
    if (t < 128) fB1[t] = bias1[t];
    if (t < 64)  fB2[t] = bias2[t];

    {
        const uint4* src = (const uint4*)wp;
        uint4* dst = (uint4*)(smem + SMM_WH);
        for (int i = t; i < WP_BYTES / 16; i += 256) dst[i] = src[i];
    }

    for (int i4 = t; i4 < 4096; i4 += 256) {
        int r = i4 >> 5;
        int c4 = i4 & 31;
        int k0 = c4 * 4;
        float4 v = make_float4(0.f, 0.f, 0.f, 0.f);
        int gr = row0 + r;
        if (gr < nrows) v = ((const float4*)(agg + (size_t)gr * FDIM))[c4];
        unsigned short hx, lx, hy, ly, hz, lz, hw, lw;
        split_bf16(v.x, hx, lx);
        split_bf16(v.y, hy, ly);
        split_bf16(v.z, hz, lz);
        split_bf16(v.w, hw, lw);
        uint32_t o = (uint32_t)(r * LDW + k0) * 2;
        uint2 hv = make_uint2((uint32_t)hx | ((uint32_t)hy << 16),
                              (uint32_t)hz | ((uint32_t)hw << 16));
        uint2 lv = make_uint2((uint32_t)lx | ((uint32_t)ly << 16),
                              (uint32_t)lz | ((uint32_t)lw << 16));
        *(uint2*)(smem + SMM_AH + o) = hv;
        *(uint2*)(smem + SMM_AL + o) = lv;
    }
    __syncthreads();

    const int m0 = wid * 16;
    const uint32_t aoff = (uint32_t)((m0 + (l & 15)) * LDW + ((l >> 4) * 8)) * 2;
    const uint32_t boff = (uint32_t)(((l & 7)) * LDW + (((l >> 3) & 1) * 8)) * 2;

    float acc[16][4];
    {
        #pragma unroll
        for (int nt = 0; nt < 16; ++nt) {
            int col = nt * 8 + 2 * (l & 3);
            float bA = fB1[col], bB = fB1[col + 1];
            acc[nt][0] = bA; acc[nt][1] = bB;
            acc[nt][2] = bA; acc[nt][3] = bB;
        }
    }
    #pragma unroll 1
    for (int kk = 0; kk < 8; ++kk) {
        uint32_t ah[4], al[4];
        ldsm4(ah, sb + SMM_AH + aoff + kk * 32);
        ldsm4(al, sb + SMM_AL + aoff + kk * 32);
        #pragma unroll
        for (int nt = 0; nt < 16; ++nt) {
            uint32_t bh[2], bl_[2];
            uint32_t bb = boff + nt * (8 * LDW * 2) + kk * 32;
            ldsm2(bh,  sb + SMM_WH + bb);
            ldsm2(bl_, sb + SMM_WL + bb);
            mma_bf16(acc[nt], ah, bh);
            mma_bf16(acc[nt], al, bh);
            mma_bf16(acc[nt], ah, bl_);
        }
    }

    {
        int r1 = m0 + (l >> 2);
        int r2 = r1 + 8;
        #pragma unroll
        for (int nt = 0; nt < 16; ++nt) {
            int col = nt * 8 + 2 * (l & 3);
            float v0 = acc[nt][0], v1 = acc[nt][1];
            float v2 = acc[nt][2], v3 = acc[nt][3];
            v0 = v0 > 0.f ? v0 : 0.01f * v0;
            v1 = v1 > 0.f ? v1 : 0.01f * v1;
            v2 = v2 > 0.f ? v2 : 0.01f * v2;
            v3 = v3 > 0.f ? v3 : 0.01f * v3;
            unsigned short h0, l0, h1, l1, h2, l2, h3, l3;
            split_bf16(v0, h0, l0);
            split_bf16(v1, h1, l1);
            split_bf16(v2, h2, l2);
            split_bf16(v3, h3, l3);
            uint32_t o1 = (uint32_t)(r1 * LDW + col) * 2;
            uint32_t o2 = (uint32_t)(r2 * LDW + col) * 2;
            *(uint32_t*)(smem + SMM_AH + o1) = (uint32_t)h0 | ((uint32_t)h1 << 16);
            *(uint32_t*)(smem + SMM_AL + o1) = (uint32_t)l0 | ((uint32_t)l1 << 16);
            *(uint32_t*)(smem + SMM_AH + o2) = (uint32_t)h2 | ((uint32_t)h3 << 16);
            *(uint32_t*)(smem + SMM_AL + o2) = (uint32_t)l2 | ((uint32_t)l3 << 16);
        }
    }
    __syncwarp();

    float acc2[8][4];
    {
        #pragma unroll
        for (int nt = 0; nt < 8; ++nt) {
            int col = nt * 8 + 2 * (l & 3);
            float bA = fB2[col], bB = fB2[col + 1];
            acc2[nt][0] = bA; acc2[nt][1] = bB;
            acc2[nt][2] = bA; acc2[nt][3] = bB;
        }
    }
    #pragma unroll 1
    for (int kk = 0; kk < 8; ++kk) {
        uint32_t ah[4], al[4];
        ldsm4(ah, sb + SMM_AH + aoff + kk * 32);
        ldsm4(al, sb + SMM_AL + aoff + kk * 32);
        #pragma unroll
        for (int nt = 0; nt < 8; ++nt) {
            uint32_t bh[2], bl_[2];
            uint32_t bb = boff + nt * (8 * LDW * 2) + kk * 32;
            ldsm2(bh,  sb + SMM_W2H + bb);
            ldsm2(bl_, sb + SMM_W2L + bb);
            mma_bf16(acc2[nt], ah, bh);
            mma_bf16(acc2[nt], al, bh);
            mma_bf16(acc2[nt], ah, bl_);
        }
    }

    {
        int r1 = row0 + m0 + (l >> 2);
        int r2 = r1 + 8;
        #pragma unroll
        for (int nt = 0; nt < 8; ++nt) {
            int col = nt * 8 + 2 * (l & 3);
            if (r1 < nrows)
                *(float2*)(out + (size_t)r1 * ODIM + col) =
                    make_float2(acc2[nt][0], acc2[nt][1]);
            if (r2 < nrows)
                *(float2*)(out + (size_t)r2 * ODIM + col) =
                    make_float2(acc2[nt][2], acc2[nt][3]);
        }
    }
}

// ---------------- cleanup (launch 6) ----------------
__global__ void cleanup_kernel() {
    const size_t T = (size_t)gridDim.x * blockDim.x;
    const size_t i0 = (size_t)blockIdx.x * blockDim.x + threadIdx.x;
    for (size_t i = i0; i < N_SVC;  i += T) { g_cs_svc[i] = 0; g_cd_svc[i] = 0; }
    for (size_t i = i0; i < N_POD;  i += T) { g_cs_pn[i]  = 0; g_cd_np[i]  = 0; }
    for (size_t i = i0; i < N_NODE; i += T) { g_cd_pn[i]  = 0; g_cs_np[i]  = 0; }
    if (i0 < 3) g_tot[i0] = 0;
}

// ---------------- host launcher ----------------

static inline int cdiv(long long a, long long b) { return (int)((a + b - 1) / b); }

extern "C" void kernel_launch(void* const* d_in, const int* in_sizes, int n_in,
                              void* d_out, int out_size) {
    const float* x_svc  = (const float*)d_in[0];
    const float* x_pod  = (const float*)d_in[1];
    const float* x_node = (const float*)d_in[2];
    const int* svc_src = (const int*)d_in[3];
    const int* svc_dst = (const int*)d_in[4];
    const int* pn_src  = (const int*)d_in[5];
    const int* pn_dst  = (const int*)d_in[6];
    const int* np_src  = (const int*)d_in[7];
    const int* np_dst  = (const int*)d_in[8];
    const float* W_call = (const float*)d_in[9];
    const float* b_call = (const float*)d_in[10];
    const float* W_in   = (const float*)d_in[11];
    const float* b_in   = (const float*)d_in[12];
    const float* W_ni   = (const float*)d_in[13];
    const float* b_ni   = (const float*)d_in[14];
    const float* W_lin_svc  = (const float*)d_in[15];
    const float* b_lin_svc  = (const float*)d_in[16];
    const float* W_lin_node = (const float*)d_in[17];
    const float* b_lin_node = (const float*)d_in[18];
    const float* W_lin_pod  = (const float*)d_in[19];
    const float* b_lin_pod  = (const float*)d_in[20];
    float* out = (float*)d_out;

    const int E_SVC = in_sizes[3];
    const int E_PN  = in_sizes[5];
    const int E_NP  = in_sizes[7];

    float *agg_svc, *agg_node, *agg_pod;
    cudaGetSymbolAddress((void**)&agg_svc,  g_agg_svc);
    cudaGetSymbolAddress((void**)&agg_node, g_agg_node);
    cudaGetSymbolAddress((void**)&agg_pod,  g_agg_pod);

    const int TB = 256;
    const long long Q_TOT = (long long)((E_SVC + 3) / 4) + (E_PN + 3) / 4 + (E_NP + 3) / 4;

    // 0: weight prep (independent of graph passes)
    wprep_kernel<<<cdiv(3 * 12288, TB), TB>>>(W_call, W_lin_svc,
                                              W_in,   W_lin_node,
                                              W_ni,   W_lin_pod);
    // 1: degree counts (vectorized)
    cnt_all_kernel<<<cdiv(Q_TOT, TB), TB>>>(svc_src, svc_dst, pn_src, pn_dst,
                                            np_src, np_dst, E_SVC, E_PN, E_NP);
    // 2: rs arrays + warp-aggregated CSR offsets
    alloc_all_kernel<<<cdiv(N_POD, TB), TB>>>();
    // 3: bin edges by dst (ncu capture target)
    bin_all_kernel<<<cdiv(Q_TOT, TB), TB>>>(svc_src, svc_dst, pn_src, pn_dst,
                                            np_src, np_dst, E_SVC, E_PN, E_NP);
    // 4: all gathers in one launch
    gather_all_kernel<<<cdiv((long long)(N_SVC + N_NODE + N_POD) * 32, TB), TB>>>(
        x_svc, x_pod, x_node);
    // 5: fused mma.sync GEMM
    cudaFuncSetAttribute(fused_mma_kernel, cudaFuncAttributeMaxDynamicSharedMemorySize,
                         SMM_TOTAL);
    fused_mma_kernel<<<B_SVC_BLKS + B_NODE_BLKS + B_POD_BLKS, 256, SMM_TOTAL>>>(
        agg_svc,  b_call, b_lin_svc,
        agg_node, b_in,   b_lin_node,
        agg_pod,  b_ni,   b_lin_pod,
        out);
    // 6: reset counters for next call
    cleanup_kernel<<<256, TB>>>();
}